// round 8
// baseline (speedup 1.0000x reference)
#include <cuda_runtime.h>
#include <math.h>

#define BB   4
#define NN   1024
#define CDIM 256
#define HH   4
#define DKK  64
#define GG   4
#define BH   (BB*HH)

// ---------------- scratch (device globals; no allocation) ----------------
__device__ float g_S   [(size_t)BH * NN * NN];   // raw cosine-relu matrix [bh][i][j]
__device__ int   g_ok  [NN];                     // diag-domination mask
__device__ int   g_allok;                        // 1 if vec == all-ones exactly
__device__ float g_vec [NN];                     // top-k union mask
__device__ float g_colw[(size_t)BB * NN];        // 0.25*sm[b,j]*vec[j]
__device__ float g_fmv [(size_t)BB * NN];        // 0.25*(sm[b,i]==0)
__device__ float g_pre [(size_t)BB * CDIM * NN]; // gconv output (stage1/2)
__device__ float g_out1[(size_t)BB * CDIM * NN]; // stage1 result (B,C,n)
__device__ float g_o1T [(size_t)BB * NN * CDIM]; // stage1 result (B,n,C)
__device__ float g_o2m [(size_t)BB * CDIM * NN]; // stage2 message

// ---------------- f32x2 helpers ----------------
typedef unsigned long long ull;
__device__ __forceinline__ void ffma2(ull& d, ull a, ull b) {
    asm("fma.rn.f32x2 %0, %1, %2, %0;" : "+l"(d) : "l"(a), "l"(b));
}
__device__ __forceinline__ ull pk(float x, float y) {
    ull r; asm("mov.b64 %0, {%1, %2};" : "=l"(r) : "f"(x), "f"(y)); return r;
}
__device__ __forceinline__ float lo2(ull a) { return __uint_as_float((unsigned)a); }
__device__ __forceinline__ float hi2(ull a) { return __uint_as_float((unsigned)(a >> 32)); }

// swizzled [k][m] index, pitch 68; float4-contiguous in m for fixed k
__device__ __forceinline__ int swidx(int k, int m) {
    return k * 68 + (((((m) >> 2) ^ (k & 15)) << 2) | (m & 3));
}

// ---------------- kernels ----------------

// Symmetric cosine GEMM (FFMA2 micro), norms in-tile, zeroes okmask in one block.
// Computes only lower-tri tiles (jt>=it), mirror-writes the transpose.
__global__ __launch_bounds__(256) void cos_gemm_sym_kernel(
        const float* __restrict__ X, float* __restrict__ S, int* __restrict__ okmask) {
    int bh = blockIdx.y, b = bh >> 2, h = bh & 3;
    int t = blockIdx.x;               // 0..135 tri-tile index
    if (t == 0 && bh == 0) {
        int q = threadIdx.x;
        okmask[q] = 0; okmask[q + 256] = 0; okmask[q + 512] = 0; okmask[q + 768] = 0;
    }
    int tr = (int)((sqrtf(8.0f * (float)t + 1.0f) - 1.0f) * 0.5f);
    while ((tr + 1) * (tr + 2) / 2 <= t) tr++;
    while (tr * (tr + 1) / 2 > t) tr--;
    int tc = t - tr * (tr + 1) / 2;   // tc <= tr
    int it = tc * 64, jt = tr * 64;   // jt >= it

    __shared__ __align__(16) float sA[64 * 68];   // swizzled [k][m]
    __shared__ __align__(16) float sB[64 * 68];   // swizzled [k][n]
    __shared__ float nish[64], njsh[64];
    int tid = threadIdx.x;
    const float* Abase = X + ((size_t)(b * NN + it)) * CDIM + h * DKK;
    const float* Bbase = X + ((size_t)(b * NN + jt)) * CDIM + h * DKK;
    #pragma unroll
    for (int l = 0; l < 4; l++) {
        int idx = tid + l * 256;
        int rr = idx >> 4, c4 = idx & 15;
        float4 va = *(const float4*)(Abase + (size_t)rr * CDIM + c4 * 4);
        float4 vb = *(const float4*)(Bbase + (size_t)rr * CDIM + c4 * 4);
        sA[swidx(c4*4+0, rr)] = va.x; sA[swidx(c4*4+1, rr)] = va.y;
        sA[swidx(c4*4+2, rr)] = va.z; sA[swidx(c4*4+3, rr)] = va.w;
        sB[swidx(c4*4+0, rr)] = vb.x; sB[swidx(c4*4+1, rr)] = vb.y;
        sB[swidx(c4*4+2, rr)] = vb.z; sB[swidx(c4*4+3, rr)] = vb.w;
    }
    __syncthreads();
    // in-tile norms: threads 0..63 -> rows of A, 64..127 -> rows of B
    if (tid < 64) {
        float s = 0.0f;
        #pragma unroll 16
        for (int k = 0; k < DKK; k++) { float v = sA[swidx(k, tid)]; s += v * v; }
        nish[tid] = sqrtf(s);
    } else if (tid < 128) {
        int n = tid - 64;
        float s = 0.0f;
        #pragma unroll 16
        for (int k = 0; k < DKK; k++) { float v = sB[swidx(k, n)]; s += v * v; }
        njsh[n] = sqrtf(s);
    }
    int ty = tid >> 4, tx = tid & 15;
    ull d00 = 0, d01 = 0, d10 = 0, d11 = 0;
    ull a00 = 0, a01 = 0, a10 = 0, a11 = 0;
    #pragma unroll
    for (int k = 0; k < DKK; k++) {
        float4 af = *(const float4*)&sA[k * 68 + ((ty ^ (k & 15)) << 2)];
        float4 bf = *(const float4*)&sB[k * 68 + ((tx ^ (k & 15)) << 2)];
        ull A01 = pk(af.x, af.y), A23 = pk(af.z, af.w);
        ull B01 = pk(bf.x, bf.y), B23 = pk(bf.z, bf.w);
        ull B10 = pk(bf.y, bf.x), B32 = pk(bf.w, bf.z);
        ffma2(d00, A01, B01); ffma2(a00, A01, B10);
        ffma2(d01, A01, B23); ffma2(a01, A01, B32);
        ffma2(d10, A23, B01); ffma2(a10, A23, B10);
        ffma2(d11, A23, B23); ffma2(a11, A23, B32);
    }
    float acc[4][4];
    acc[0][0] = lo2(d00); acc[1][1] = hi2(d00); acc[0][1] = lo2(a00); acc[1][0] = hi2(a00);
    acc[0][2] = lo2(d01); acc[1][3] = hi2(d01); acc[0][3] = lo2(a01); acc[1][2] = hi2(a01);
    acc[2][0] = lo2(d10); acc[3][1] = hi2(d10); acc[2][1] = lo2(a10); acc[3][0] = hi2(a10);
    acc[2][2] = lo2(d11); acc[3][3] = hi2(d11); acc[2][3] = lo2(a11); acc[3][2] = hi2(a11);
    __syncthreads();                               // nish/njsh ready
    float ni[4], nj[4];
    #pragma unroll
    for (int u = 0; u < 4; u++) ni[u] = nish[ty * 4 + u];
    #pragma unroll
    for (int v = 0; v < 4; v++) nj[v] = njsh[tx * 4 + v];
    float* Sout = S + (size_t)bh * NN * NN;
    float sv[4][4];
    #pragma unroll
    for (int u = 0; u < 4; u++)
        #pragma unroll
        for (int v = 0; v < 4; v++) {
            float d = fmaxf(ni[u] * nj[v], 1e-8f);
            sv[u][v] = fmaxf(acc[u][v] / d, 0.0f);
            Sout[(size_t)(it + ty * 4 + u) * NN + jt + tx * 4 + v] = sv[u][v];
        }
    if (it != jt) {
        __syncthreads();                           // compute reads of sA done
        float* T = sA;                             // 64 x 68 plain stage
        #pragma unroll
        for (int u = 0; u < 4; u++)
            #pragma unroll
            for (int v = 0; v < 4; v++)
                T[(tx * 4 + v) * 68 + ty * 4 + u] = sv[u][v];
        __syncthreads();
        #pragma unroll
        for (int l = 0; l < 4; l++) {
            int idx = tid + l * 256;
            int rr = idx >> 4, c4 = idx & 15;
            float4 o = *(const float4*)&T[rr * 68 + c4 * 4];
            *(float4*)&Sout[(size_t)(jt + rr) * NN + it + c4 * 4] = o;
        }
    }
}

// Exact check: is index i in top-4 of row (bh,i)? Counts entries that precede
// the diagonal in jax.lax.top_k order (desc value, ties -> lower index).
__global__ void diagcheck_kernel(const float* __restrict__ S, int* __restrict__ okmask) {
    int row  = blockIdx.x * 8 + (threadIdx.x >> 5);
    int lane = threadIdx.x & 31;
    int i = row & (NN - 1);
    const float* p = S + (size_t)row * NN;
    float d = p[i];
    int cnt = 0;
    #pragma unroll
    for (int l = 0; l < 8; l++) {
        int j0 = lane * 4 + l * 128;
        float4 x = *(const float4*)(p + j0);
        cnt += (x.x > d || (x.x == d && (j0 + 0) < i));
        cnt += (x.y > d || (x.y == d && (j0 + 1) < i));
        cnt += (x.z > d || (x.z == d && (j0 + 2) < i));
        cnt += (x.w > d || (x.w == d && (j0 + 3) < i));
    }
    #pragma unroll
    for (int off = 16; off; off >>= 1) cnt += __shfl_xor_sync(0xffffffffu, cnt, off);
    if (lane == 0 && cnt < 4) okmask[i] = 1;   // races: all write 1, benign
}

// vec[j] = okmask[j]; allok = AND_j okmask[j]. One block of 1024.
__global__ void vecfinal_kernel(const int* __restrict__ okmask,
                                float* __restrict__ vec, int* __restrict__ allok) {
    int j = threadIdx.x;
    int ok = okmask[j];
    vec[j] = ok ? 1.0f : 0.0f;
    int all = __syncthreads_and(ok);
    if (j == 0) *allok = all ? 1 : 0;
}

// Fallback exact top-4 union; early-exits when diag-domination proved vec==1.
__global__ void topk_kernel(const float* __restrict__ S, float* __restrict__ vec,
                            const int* __restrict__ allok) {
    if (*allok) return;
    int row  = blockIdx.x * (blockDim.x >> 5) + (threadIdx.x >> 5);
    int lane = threadIdx.x & 31;
    if (row >= BH * NN) return;
    const float* p = S + (size_t)row * NN;
    float v[4] = {-1e30f, -1e30f, -1e30f, -1e30f};
    int   id[4] = {0, 0, 0, 0};
    for (int j = lane; j < NN; j += 32) {
        float x = p[j];
        if (x > v[3]) {
            if (x > v[0])      { v[3]=v[2];id[3]=id[2]; v[2]=v[1];id[2]=id[1]; v[1]=v[0];id[1]=id[0]; v[0]=x; id[0]=j; }
            else if (x > v[1]) { v[3]=v[2];id[3]=id[2]; v[2]=v[1];id[2]=id[1]; v[1]=x; id[1]=j; }
            else if (x > v[2]) { v[3]=v[2];id[3]=id[2]; v[2]=x; id[2]=j; }
            else               { v[3]=x; id[3]=j; }
        }
    }
    #pragma unroll
    for (int r = 0; r < 4; r++) {
        float best = v[0]; int bl = lane;
        #pragma unroll
        for (int off = 16; off; off >>= 1) {
            float ov = __shfl_xor_sync(0xffffffffu, best, off);
            int   ol = __shfl_xor_sync(0xffffffffu, bl, off);
            if (ov > best || (ov == best && ol < bl)) { best = ov; bl = ol; }
        }
        int widx = __shfl_sync(0xffffffffu, id[0], bl);
        if (lane == 0) vec[widx] = 1.0f;
        if (lane == bl) { v[0]=v[1];id[0]=id[1]; v[1]=v[2];id[1]=id[2]; v[2]=v[3];id[2]=id[3]; v[3]=-1e30f; }
    }
}

// colw[b,j] = 0.25*sm[b,j]*vec[j];  fmv[b,i] = 0.25*(sm[b,i]==0)
__global__ void colprep_kernel(const int* __restrict__ smask, const float* __restrict__ vec,
                               float* __restrict__ colw, float* __restrict__ fmv) {
    int b = blockIdx.x, j = threadIdx.x;
    int s = smask[(size_t)b * NN + j];
    colw[(size_t)b * NN + j] = 0.25f * (float)s * vec[j];
    fmv [(size_t)b * NN + j] = (s == 0) ? 0.25f : 0.0f;
}

// grouped 1x1 conv + relu. Xin node-major (B,NN,CDIM); out (B,CDIM,NN).
__global__ __launch_bounds__(256) void gconv_kernel(
        const float* __restrict__ Xin, const float* __restrict__ W,
        const float* __restrict__ bias, float* __restrict__ out) {
    int b = blockIdx.z, g = blockIdx.y, nt = blockIdx.x * 64;
    __shared__ float Wst[64][65];    // [ci][o]
    __shared__ float Xst[64][65];    // [ci][n]
    int tid = threadIdx.x;
    const float* Wb = W + (size_t)g * 64 * 64;
    const float* Xb = Xin + ((size_t)b * NN + nt) * CDIM + g * 64;
    #pragma unroll
    for (int l = 0; l < 4; l++) {
        int idx = tid + l * 256; int r = idx >> 4, c4 = idx & 15;
        float4 w4 = *(const float4*)(Wb + (size_t)r * 64 + c4 * 4);
        Wst[c4*4+0][r] = w4.x; Wst[c4*4+1][r] = w4.y; Wst[c4*4+2][r] = w4.z; Wst[c4*4+3][r] = w4.w;
        float4 x4 = *(const float4*)(Xb + (size_t)r * CDIM + c4 * 4);
        Xst[c4*4+0][r] = x4.x; Xst[c4*4+1][r] = x4.y; Xst[c4*4+2][r] = x4.z; Xst[c4*4+3][r] = x4.w;
    }
    __syncthreads();
    int ty = tid >> 4, tx = tid & 15;
    float acc[4][4] = {};
    #pragma unroll 16
    for (int k = 0; k < 64; k++) {
        float a[4], bv[4];
        #pragma unroll
        for (int u = 0; u < 4; u++) a[u]  = Wst[k][ty * 4 + u];
        #pragma unroll
        for (int v = 0; v < 4; v++) bv[v] = Xst[k][tx * 4 + v];
        #pragma unroll
        for (int u = 0; u < 4; u++)
            #pragma unroll
            for (int v = 0; v < 4; v++) acc[u][v] += a[u] * bv[v];
    }
    #pragma unroll
    for (int u = 0; u < 4; u++) {
        int oc = g * 64 + ty * 4 + u;
        float bs = bias[oc];
        #pragma unroll
        for (int v = 0; v < 4; v++) {
            float val = fmaxf(acc[u][v] + bs, 0.0f);
            out[((size_t)b * CDIM + oc) * NN + nt + tx * 4 + v] = val;
        }
    }
}

// Fused message GEMM (FFMA2 micro) with on-the-fly mask:
// o[b,h*64+cc,i] = sum_j U[b,h*64+cc,j] * A[bh,i,j]  (+ pre if given),
// A[bh,i,j] = S[bh,i,j]*mroi[b,i,j]*colw[b,j] + (j==i)*fmv[b,i]
__global__ __launch_bounds__(256) void ogemm_fused_kernel(
        const float* __restrict__ U, const float* __restrict__ S,
        const int* __restrict__ mroi, const float* __restrict__ colw,
        const float* __restrict__ fmv,
        const float* __restrict__ pre, float* __restrict__ out) {
    int bh = blockIdx.y, b = bh >> 2, h = bh & 3;
    int it = blockIdx.x * 64;
    __shared__ __align__(16) float sU[64 * 68];   // swizzled [k][cc]
    __shared__ __align__(16) float sM[64 * 68];   // swizzled [k][i] (masked A)
    const float* Ub = U  + ((size_t)b * CDIM + h * 64) * NN;
    const float* Sb = S  + ((size_t)bh * NN + it) * NN;
    const int*   Mb = mroi + ((size_t)b * NN + it) * NN;
    const float* cw = colw + (size_t)b * NN;
    const float* fv = fmv  + (size_t)b * NN + it;
    int tid = threadIdx.x, ty = tid >> 4, tx = tid & 15;
    ull d00 = 0, d01 = 0, d10 = 0, d11 = 0;
    ull a00 = 0, a01 = 0, a10 = 0, a11 = 0;
    for (int k0 = 0; k0 < NN; k0 += 64) {
        #pragma unroll
        for (int l = 0; l < 4; l++) {
            int idx = tid + l * 256; int r = idx >> 4, c4 = idx & 15;
            float4 u4 = *(const float4*)(Ub + (size_t)r * NN + k0 + c4 * 4);
            sU[swidx(c4*4+0, r)] = u4.x; sU[swidx(c4*4+1, r)] = u4.y;
            sU[swidx(c4*4+2, r)] = u4.z; sU[swidx(c4*4+3, r)] = u4.w;
            float4 s4 = *(const float4*)(Sb + (size_t)r * NN + k0 + c4 * 4);
            int4   m4 = *(const int4*)  (Mb + (size_t)r * NN + k0 + c4 * 4);
            float4 w4 = *(const float4*)(cw + k0 + c4 * 4);
            float  fm = fv[r];
            int jb = k0 + c4 * 4, ig = it + r;
            sM[swidx(c4*4+0, r)] = s4.x * (float)m4.x * w4.x + ((jb + 0 == ig) ? fm : 0.0f);
            sM[swidx(c4*4+1, r)] = s4.y * (float)m4.y * w4.y + ((jb + 1 == ig) ? fm : 0.0f);
            sM[swidx(c4*4+2, r)] = s4.z * (float)m4.z * w4.z + ((jb + 2 == ig) ? fm : 0.0f);
            sM[swidx(c4*4+3, r)] = s4.w * (float)m4.w * w4.w + ((jb + 3 == ig) ? fm : 0.0f);
        }
        __syncthreads();
        #pragma unroll
        for (int k = 0; k < 64; k++) {
            float4 af = *(const float4*)&sU[k * 68 + ((ty ^ (k & 15)) << 2)];
            float4 bf = *(const float4*)&sM[k * 68 + ((tx ^ (k & 15)) << 2)];
            ull A01 = pk(af.x, af.y), A23 = pk(af.z, af.w);
            ull B01 = pk(bf.x, bf.y), B23 = pk(bf.z, bf.w);
            ull B10 = pk(bf.y, bf.x), B32 = pk(bf.w, bf.z);
            ffma2(d00, A01, B01); ffma2(a00, A01, B10);
            ffma2(d01, A01, B23); ffma2(a01, A01, B32);
            ffma2(d10, A23, B01); ffma2(a10, A23, B10);
            ffma2(d11, A23, B23); ffma2(a11, A23, B32);
        }
        __syncthreads();
    }
    float acc[4][4];
    acc[0][0] = lo2(d00); acc[1][1] = hi2(d00); acc[0][1] = lo2(a00); acc[1][0] = hi2(a00);
    acc[0][2] = lo2(d01); acc[1][3] = hi2(d01); acc[0][3] = lo2(a01); acc[1][2] = hi2(a01);
    acc[2][0] = lo2(d10); acc[3][1] = hi2(d10); acc[2][1] = lo2(a10); acc[3][0] = hi2(a10);
    acc[2][2] = lo2(d11); acc[3][3] = hi2(d11); acc[2][3] = lo2(a11); acc[3][2] = hi2(a11);
    #pragma unroll
    for (int u = 0; u < 4; u++) {
        int oc = h * 64 + ty * 4 + u;
        #pragma unroll
        for (int v = 0; v < 4; v++) {
            size_t o = ((size_t)b * CDIM + oc) * NN + it + tx * 4 + v;
            float val = acc[u][v];
            if (pre != nullptr) val += pre[o];
            out[o] = val;
        }
    }
}

// (B,CDIM,NN) -> (B,NN,CDIM)
__global__ void transpose_kernel(const float* __restrict__ in, float* __restrict__ out) {
    __shared__ float t[32][33];
    int b = blockIdx.z;
    int c0 = blockIdx.y * 32, n0 = blockIdx.x * 32;
    int x = threadIdx.x, y = threadIdx.y;
    for (int yy = y; yy < 32; yy += 8)
        t[yy][x] = in[((size_t)b * CDIM + c0 + yy) * NN + n0 + x];
    __syncthreads();
    for (int yy = y; yy < 32; yy += 8)
        out[((size_t)b * NN + n0 + yy) * CDIM + c0 + x] = t[x][yy];
}

// gts[m,o] = relu(sum_c F[m,c]*W[o,c] + b[o]),  m = b*NN+n
__global__ __launch_bounds__(256) void gts_kernel(
        const float* __restrict__ F, const float* __restrict__ W,
        const float* __restrict__ bias, float* __restrict__ out) {
    int mt = blockIdx.y * 64, ntc = blockIdx.x * 64;
    __shared__ float Fst[64][65];
    __shared__ float Wst[64][65];
    int tid = threadIdx.x, ty = tid >> 4, tx = tid & 15;
    float acc[4][4] = {};
    for (int k0 = 0; k0 < CDIM; k0 += 64) {
        #pragma unroll
        for (int l = 0; l < 4; l++) {
            int idx = tid + l * 256; int r = idx >> 4, c4 = idx & 15;
            float4 f4 = *(const float4*)(F + (size_t)(mt + r) * CDIM + k0 + c4 * 4);
            Fst[c4*4+0][r] = f4.x; Fst[c4*4+1][r] = f4.y; Fst[c4*4+2][r] = f4.z; Fst[c4*4+3][r] = f4.w;
            float4 w4 = *(const float4*)(W + (size_t)(ntc + r) * CDIM + k0 + c4 * 4);
            Wst[c4*4+0][r] = w4.x; Wst[c4*4+1][r] = w4.y; Wst[c4*4+2][r] = w4.z; Wst[c4*4+3][r] = w4.w;
        }
        __syncthreads();
        #pragma unroll 16
        for (int k = 0; k < 64; k++) {
            float a[4], bv[4];
            #pragma unroll
            for (int u = 0; u < 4; u++) a[u]  = Fst[k][ty * 4 + u];
            #pragma unroll
            for (int v = 0; v < 4; v++) bv[v] = Wst[k][tx * 4 + v];
            #pragma unroll
            for (int u = 0; u < 4; u++)
                #pragma unroll
                for (int v = 0; v < 4; v++) acc[u][v] += a[u] * bv[v];
        }
        __syncthreads();
    }
    #pragma unroll
    for (int u = 0; u < 4; u++)
        #pragma unroll
        for (int v = 0; v < 4; v++) {
            int oc = ntc + tx * 4 + v;
            float val = fmaxf(acc[u][v] + bias[oc], 0.0f);
            out[(size_t)(mt + ty * 4 + u) * CDIM + oc] = val;
        }
}

// LayerNorm over channels of y[b,n,c] = o2m[b,c,n]; writes node_feat and out0.
__global__ void final_kernel(const float* __restrict__ o2m,
                             const float* __restrict__ out2pre,
                             const float* __restrict__ lnw, const float* __restrict__ lnb,
                             float* __restrict__ out0, float* __restrict__ outnf) {
    int b = blockIdx.y, n = blockIdx.x;
    int c = threadIdx.x;
    float y = o2m[((size_t)b * CDIM + c) * NN + n];
    __shared__ float s1[256], s2[256];
    s1[c] = y; s2[c] = y * y;
    __syncthreads();
    for (int st = 128; st; st >>= 1) {
        if (c < st) { s1[c] += s1[c + st]; s2[c] += s2[c + st]; }
        __syncthreads();
    }
    float mu  = s1[0] * (1.0f / CDIM);
    float var = s2[0] * (1.0f / CDIM) - mu * mu;
    float rstd = rsqrtf(fmaxf(var, 0.0f) + 1e-6f);
    float nf = (y - mu) * rstd * lnw[c] + lnb[c];
    size_t oidx = ((size_t)b * NN + n) * CDIM + c;
    outnf[oidx] = nf;
    out0[oidx]  = out2pre[((size_t)b * CDIM + c) * NN + n] + nf;
}

// ---------------- launcher ----------------
extern "C" void kernel_launch(void* const* d_in, const int* in_sizes, int n_in,
                              void* d_out, int out_size) {
    (void)in_sizes; (void)n_in; (void)out_size;
    const float* input   = (const float*)d_in[0];
    const int*   mroi    = (const int*)  d_in[1];
    const int*   smask   = (const int*)  d_in[2];
    const float* gt_feat = (const float*)d_in[3];
    const float* w1      = (const float*)d_in[4];
    const float* b1      = (const float*)d_in[5];
    const float* w2      = (const float*)d_in[6];
    const float* b2      = (const float*)d_in[7];
    const float* gt_w    = (const float*)d_in[8];
    const float* gt_b    = (const float*)d_in[9];
    const float* lnw     = (const float*)d_in[10];
    const float* lnb     = (const float*)d_in[11];

    float* out0    = (float*)d_out;                           // out2.T (B,NN,C)
    float* out_gts = out0 + (size_t)BB * NN * CDIM;           // gts
    float* out_nf  = out0 + 2 * (size_t)BB * NN * CDIM;       // node_feat

    float *S, *vec, *colw, *fmv, *pre, *out1, *o1T, *o2m;
    int *okm, *allok;
    cudaGetSymbolAddress((void**)&S,     g_S);
    cudaGetSymbolAddress((void**)&okm,   g_ok);
    cudaGetSymbolAddress((void**)&allok, g_allok);
    cudaGetSymbolAddress((void**)&vec,   g_vec);
    cudaGetSymbolAddress((void**)&colw,  g_colw);
    cudaGetSymbolAddress((void**)&fmv,   g_fmv);
    cudaGetSymbolAddress((void**)&pre,   g_pre);
    cudaGetSymbolAddress((void**)&out1,  g_out1);
    cudaGetSymbolAddress((void**)&o1T,   g_o1T);
    cudaGetSymbolAddress((void**)&o2m,   g_o2m);

    // #0 independent gts branch
    gts_kernel<<<dim3(CDIM / 64, (BB * NN) / 64), 256>>>(gt_feat, gt_w, gt_b, out_gts);
    // #1 gconv1 (independent of attention)
    gconv_kernel<<<dim3(NN / 64, GG, BB), 256>>>(input, w1, b1, pre);
    // #2 cos GEMM (zeroes okmask)
    cos_gemm_sym_kernel<<<dim3(136, BH), 256>>>(input, S, okm);
    // #3 exact diag-domination counts
    diagcheck_kernel<<<(BH * NN) / 8, 256>>>(S, okm);
    // #4 vec + allok
    vecfinal_kernel<<<1, NN>>>(okm, vec, allok);
    // #5 exact fallback (early-exits when allok)
    topk_kernel<<<(BH * NN) / 8, 256>>>(S, vec, allok);
    // #6 column/diag prep
    colprep_kernel<<<BB, NN>>>(smask, vec, colw, fmv);
    // #7 fused mask + message GEMM: out1 = pre + msg
    ogemm_fused_kernel<<<dim3(NN / 64, BH), 256>>>(pre, S, mroi, colw, fmv, pre, out1);
    // #8 transpose to node-major
    transpose_kernel<<<dim3(NN / 32, CDIM / 32, BB), dim3(32, 8)>>>(out1, o1T);

    // ---- stage 2 ----
    cos_gemm_sym_kernel<<<dim3(136, BH), 256>>>(o1T, S, okm);
    diagcheck_kernel<<<(BH * NN) / 8, 256>>>(S, okm);
    vecfinal_kernel<<<1, NN>>>(okm, vec, allok);
    topk_kernel<<<(BH * NN) / 8, 256>>>(S, vec, allok);
    colprep_kernel<<<BB, NN>>>(smask, vec, colw, fmv);
    gconv_kernel<<<dim3(NN / 64, GG, BB), 256>>>(o1T, w2, b2, pre);      // out2_pre
    ogemm_fused_kernel<<<dim3(NN / 64, BH), 256>>>(pre, S, mroi, colw, fmv, nullptr, o2m);
    final_kernel<<<dim3(NN, BB), 256>>>(o2m, pre, lnw, lnb, out0, out_nf);
}

// round 9
// speedup vs baseline: 1.2925x; 1.2925x over previous
#include <cuda_runtime.h>
#include <math.h>

#define BB   4
#define NN   1024
#define CDIM 256
#define HH   4
#define DKK  64
#define GG   4
#define BH   (BB*HH)

// ---------------- scratch (device globals; no allocation) ----------------
__device__ float g_S   [(size_t)BH * NN * NN];   // raw cosine-relu matrix [bh][i][j]
__device__ int   g_ok  [NN];                     // diag-domination mask
__device__ int   g_allok;                        // 1 if vec == all-ones exactly
__device__ float g_vec [NN];                     // top-k union mask
__device__ int   g_idxc[(size_t)BB * NN];        // compacted surviving-column indices
__device__ float g_cwc [(size_t)BB * NN];        // compacted column weights
__device__ int   g_cntp[BB];                     // padded compacted count per batch
__device__ float g_fmv [(size_t)BB * NN];        // 0.25*(sm[b,i]==0)
__device__ float g_pre [(size_t)BB * CDIM * NN]; // gconv output (stage1/2)
__device__ float g_out1[(size_t)BB * CDIM * NN]; // stage1 result (B,C,n)
__device__ float g_o1T [(size_t)BB * NN * CDIM]; // stage1 result (B,n,C)
__device__ float g_o2m [(size_t)BB * CDIM * NN]; // stage2 message

// ---------------- kernels ----------------

// Symmetric cosine GEMM (R7 scalar micro), norms in-tile, zeroes okmask in one block.
// Computes only lower-tri tiles (jt>=it), mirror-writes the transpose.
__global__ __launch_bounds__(256) void cos_gemm_sym_kernel(
        const float* __restrict__ X, float* __restrict__ S, int* __restrict__ okmask) {
    int bh = blockIdx.y, b = bh >> 2, h = bh & 3;
    int t = blockIdx.x;               // 0..135 tri-tile index
    if (t == 0 && bh == 0) {
        int q = threadIdx.x;
        okmask[q] = 0; okmask[q + 256] = 0; okmask[q + 512] = 0; okmask[q + 768] = 0;
    }
    int tr = (int)((sqrtf(8.0f * (float)t + 1.0f) - 1.0f) * 0.5f);
    while ((tr + 1) * (tr + 2) / 2 <= t) tr++;
    while (tr * (tr + 1) / 2 > t) tr--;
    int tc = t - tr * (tr + 1) / 2;   // tc <= tr
    int it = tc * 64, jt = tr * 64;   // jt >= it

    __shared__ float sbuf[2 * 64 * 65];           // A | B ; reused as transpose stage
    __shared__ float nish[64], njsh[64];
    #define AST(k,m) sbuf[(k)*65 + (m)]
    #define BST(k,n) sbuf[4160 + (k)*65 + (n)]
    int tid = threadIdx.x;
    const float* Abase = X + ((size_t)(b * NN + it)) * CDIM + h * DKK;
    const float* Bbase = X + ((size_t)(b * NN + jt)) * CDIM + h * DKK;
    #pragma unroll
    for (int l = 0; l < 4; l++) {
        int idx = tid + l * 256;
        int rr = idx >> 4, c4 = idx & 15;
        float4 va = *(const float4*)(Abase + (size_t)rr * CDIM + c4 * 4);
        float4 vb = *(const float4*)(Bbase + (size_t)rr * CDIM + c4 * 4);
        AST(c4*4+0, rr) = va.x; AST(c4*4+1, rr) = va.y; AST(c4*4+2, rr) = va.z; AST(c4*4+3, rr) = va.w;
        BST(c4*4+0, rr) = vb.x; BST(c4*4+1, rr) = vb.y; BST(c4*4+2, rr) = vb.z; BST(c4*4+3, rr) = vb.w;
    }
    __syncthreads();
    // in-tile norms: threads 0..63 -> rows of A, 64..127 -> rows of B
    if (tid < 64) {
        float s = 0.0f;
        #pragma unroll 16
        for (int k = 0; k < DKK; k++) { float v = AST(k, tid); s += v * v; }
        nish[tid] = sqrtf(s);
    } else if (tid < 128) {
        int n = tid - 64;
        float s = 0.0f;
        #pragma unroll 16
        for (int k = 0; k < DKK; k++) { float v = BST(k, n); s += v * v; }
        njsh[n] = sqrtf(s);
    }
    int ty = tid >> 4, tx = tid & 15;
    float acc[4][4] = {};
    #pragma unroll 16
    for (int k = 0; k < DKK; k++) {
        float a[4], bv[4];
        #pragma unroll
        for (int u = 0; u < 4; u++) a[u]  = AST(k, ty * 4 + u);
        #pragma unroll
        for (int v = 0; v < 4; v++) bv[v] = BST(k, tx * 4 + v);
        #pragma unroll
        for (int u = 0; u < 4; u++)
            #pragma unroll
            for (int v = 0; v < 4; v++) acc[u][v] += a[u] * bv[v];
    }
    __syncthreads();                               // nish/njsh ready
    float ni[4], nj[4];
    #pragma unroll
    for (int u = 0; u < 4; u++) ni[u] = nish[ty * 4 + u];
    #pragma unroll
    for (int v = 0; v < 4; v++) nj[v] = njsh[tx * 4 + v];
    float* Sout = S + (size_t)bh * NN * NN;
    float sv[4][4];
    #pragma unroll
    for (int u = 0; u < 4; u++)
        #pragma unroll
        for (int v = 0; v < 4; v++) {
            float d = fmaxf(ni[u] * nj[v], 1e-8f);
            sv[u][v] = fmaxf(acc[u][v] / d, 0.0f);
            Sout[(size_t)(it + ty * 4 + u) * NN + jt + tx * 4 + v] = sv[u][v];
        }
    if (it != jt) {
        __syncthreads();                           // compute reads of sbuf done
        float* T = sbuf;                           // 64 x 68 stage
        #pragma unroll
        for (int u = 0; u < 4; u++)
            #pragma unroll
            for (int v = 0; v < 4; v++)
                T[(tx * 4 + v) * 68 + ty * 4 + u] = sv[u][v];
        __syncthreads();
        #pragma unroll
        for (int l = 0; l < 4; l++) {
            int idx = tid + l * 256;
            int rr = idx >> 4, c4 = idx & 15;
            float4 o = *(const float4*)&T[rr * 68 + c4 * 4];
            *(float4*)&Sout[(size_t)(jt + rr) * NN + it + c4 * 4] = o;
        }
    }
    #undef AST
    #undef BST
}

// Exact check: is index i in top-4 of row (bh,i)? Counts entries that precede
// the diagonal in jax.lax.top_k order (desc value, ties -> lower index).
__global__ void diagcheck_kernel(const float* __restrict__ S, int* __restrict__ okmask) {
    int row  = blockIdx.x * 8 + (threadIdx.x >> 5);
    int lane = threadIdx.x & 31;
    int i = row & (NN - 1);
    const float* p = S + (size_t)row * NN;
    float d = p[i];
    int cnt = 0;
    #pragma unroll
    for (int l = 0; l < 8; l++) {
        int j0 = lane * 4 + l * 128;
        float4 x = *(const float4*)(p + j0);
        cnt += (x.x > d || (x.x == d && (j0 + 0) < i));
        cnt += (x.y > d || (x.y == d && (j0 + 1) < i));
        cnt += (x.z > d || (x.z == d && (j0 + 2) < i));
        cnt += (x.w > d || (x.w == d && (j0 + 3) < i));
    }
    #pragma unroll
    for (int off = 16; off; off >>= 1) cnt += __shfl_xor_sync(0xffffffffu, cnt, off);
    if (lane == 0 && cnt < 4) okmask[i] = 1;   // races: all write 1, benign
}

// vec[j] = okmask[j]; allok = AND_j okmask[j]. One block of 1024.
__global__ void vecfinal_kernel(const int* __restrict__ okmask,
                                float* __restrict__ vec, int* __restrict__ allok) {
    int j = threadIdx.x;
    int ok = okmask[j];
    vec[j] = ok ? 1.0f : 0.0f;
    int all = __syncthreads_and(ok);
    if (j == 0) *allok = all ? 1 : 0;
}

// Fallback exact top-4 union; early-exits when diag-domination proved vec==1.
__global__ void topk_kernel(const float* __restrict__ S, float* __restrict__ vec,
                            const int* __restrict__ allok) {
    if (*allok) return;
    int row  = blockIdx.x * (blockDim.x >> 5) + (threadIdx.x >> 5);
    int lane = threadIdx.x & 31;
    if (row >= BH * NN) return;
    const float* p = S + (size_t)row * NN;
    float v[4] = {-1e30f, -1e30f, -1e30f, -1e30f};
    int   id[4] = {0, 0, 0, 0};
    for (int j = lane; j < NN; j += 32) {
        float x = p[j];
        if (x > v[3]) {
            if (x > v[0])      { v[3]=v[2];id[3]=id[2]; v[2]=v[1];id[2]=id[1]; v[1]=v[0];id[1]=id[0]; v[0]=x; id[0]=j; }
            else if (x > v[1]) { v[3]=v[2];id[3]=id[2]; v[2]=v[1];id[2]=id[1]; v[1]=x; id[1]=j; }
            else if (x > v[2]) { v[3]=v[2];id[3]=id[2]; v[2]=x; id[2]=j; }
            else               { v[3]=x; id[3]=j; }
        }
    }
    #pragma unroll
    for (int r = 0; r < 4; r++) {
        float best = v[0]; int bl = lane;
        #pragma unroll
        for (int off = 16; off; off >>= 1) {
            float ov = __shfl_xor_sync(0xffffffffu, best, off);
            int   ol = __shfl_xor_sync(0xffffffffu, bl, off);
            if (ov > best || (ov == best && ol < bl)) { best = ov; bl = ol; }
        }
        int widx = __shfl_sync(0xffffffffu, id[0], bl);
        if (lane == 0) vec[widx] = 1.0f;
        if (lane == bl) { v[0]=v[1];id[0]=id[1]; v[1]=v[2];id[1]=id[2]; v[2]=v[3];id[2]=id[3]; v[3]=-1e30f; }
    }
}

// Per-batch compaction of surviving columns (sm[b,j]!=0), order-preserving.
// idx[b][p]=j, cwc[b][p]=0.25*vec[j]; padded to mult of 64 with (0, 0.0).
// Also writes fmv[b,i] = 0.25*(sm==0). One block of 1024 per batch.
__global__ void compact_kernel(const int* __restrict__ smask, const float* __restrict__ vec,
                               int* __restrict__ idxc, float* __restrict__ cwc,
                               int* __restrict__ cntp, float* __restrict__ fmv) {
    int b = blockIdx.x, j = threadIdx.x;
    __shared__ int ps[NN];
    int s = (smask[(size_t)b * NN + j] != 0) ? 1 : 0;
    ps[j] = s;
    __syncthreads();
    for (int off = 1; off < NN; off <<= 1) {
        int v = (j >= off) ? ps[j - off] : 0;
        __syncthreads();
        ps[j] += v;
        __syncthreads();
    }
    int total = ps[NN - 1];
    if (s) {
        int p = ps[j] - 1;
        idxc[(size_t)b * NN + p] = j;
        cwc [(size_t)b * NN + p] = 0.25f * vec[j];
    }
    int padded = (total + 63) & ~63;
    for (int p = total + j; p < padded; p += NN) {
        idxc[(size_t)b * NN + p] = 0;
        cwc [(size_t)b * NN + p] = 0.0f;
    }
    if (j == 0) cntp[b] = padded;
    fmv[(size_t)b * NN + j] = s ? 0.0f : 0.25f;
}

// grouped 1x1 conv + relu. Xin node-major (B,NN,CDIM); out (B,CDIM,NN).
__global__ __launch_bounds__(256) void gconv_kernel(
        const float* __restrict__ Xin, const float* __restrict__ W,
        const float* __restrict__ bias, float* __restrict__ out) {
    int b = blockIdx.z, g = blockIdx.y, nt = blockIdx.x * 64;
    __shared__ float Wst[64][65];    // [ci][o]
    __shared__ float Xst[64][65];    // [ci][n]
    int tid = threadIdx.x;
    const float* Wb = W + (size_t)g * 64 * 64;
    const float* Xb = Xin + ((size_t)b * NN + nt) * CDIM + g * 64;
    #pragma unroll
    for (int l = 0; l < 4; l++) {
        int idx = tid + l * 256; int r = idx >> 4, c4 = idx & 15;
        float4 w4 = *(const float4*)(Wb + (size_t)r * 64 + c4 * 4);
        Wst[c4*4+0][r] = w4.x; Wst[c4*4+1][r] = w4.y; Wst[c4*4+2][r] = w4.z; Wst[c4*4+3][r] = w4.w;
        float4 x4 = *(const float4*)(Xb + (size_t)r * CDIM + c4 * 4);
        Xst[c4*4+0][r] = x4.x; Xst[c4*4+1][r] = x4.y; Xst[c4*4+2][r] = x4.z; Xst[c4*4+3][r] = x4.w;
    }
    __syncthreads();
    int ty = tid >> 4, tx = tid & 15;
    float acc[4][4] = {};
    #pragma unroll 16
    for (int k = 0; k < 64; k++) {
        float a[4], bv[4];
        #pragma unroll
        for (int u = 0; u < 4; u++) a[u]  = Wst[k][ty * 4 + u];
        #pragma unroll
        for (int v = 0; v < 4; v++) bv[v] = Xst[k][tx * 4 + v];
        #pragma unroll
        for (int u = 0; u < 4; u++)
            #pragma unroll
            for (int v = 0; v < 4; v++) acc[u][v] += a[u] * bv[v];
    }
    #pragma unroll
    for (int u = 0; u < 4; u++) {
        int oc = g * 64 + ty * 4 + u;
        float bs = bias[oc];
        #pragma unroll
        for (int v = 0; v < 4; v++) {
            float val = fmaxf(acc[u][v] + bs, 0.0f);
            out[((size_t)b * CDIM + oc) * NN + nt + tx * 4 + v] = val;
        }
    }
}

// Compacted fused message GEMM (R7 scalar micro), k over surviving columns only:
// o[b,h*64+cc,i] = sum_{p<cnt} U[cc, idx[p]] * S[i,idx[p]]*mroi[i,idx[p]]*cwc[p]
//                  + fmv[i]*U[cc,i]  (+ pre if given)
// Bit-identical to the full sum: dropped terms are exact fp 0.0; order preserved.
__global__ __launch_bounds__(256) void ogemm_fused_kernel(
        const float* __restrict__ U, const float* __restrict__ S,
        const int* __restrict__ mroi,
        const int* __restrict__ idxc, const float* __restrict__ cwc,
        const int* __restrict__ cntp, const float* __restrict__ fmv,
        const float* __restrict__ pre, float* __restrict__ out) {
    int bh = blockIdx.y, b = bh >> 2, h = bh & 3;
    int it = blockIdx.x * 64;
    __shared__ float Ust[64][65];    // [k][cc]
    __shared__ float Ast[64][65];    // [k][i]
    const float* Ub = U  + ((size_t)b * CDIM + h * 64) * NN;
    const float* Sb = S  + ((size_t)bh * NN + it) * NN;
    const int*   Mb = mroi + ((size_t)b * NN + it) * NN;
    const int*   ib = idxc + (size_t)b * NN;
    const float* wb = cwc  + (size_t)b * NN;
    const float* fv = fmv  + (size_t)b * NN + it;
    int cnt = cntp[b];
    int tid = threadIdx.x, ty = tid >> 4, tx = tid & 15;
    float acc[4][4] = {};
    for (int k0 = 0; k0 < cnt; k0 += 64) {
        #pragma unroll
        for (int l = 0; l < 4; l++) {
            int idx = tid + l * 256; int r = idx >> 4, c4 = idx & 15;
            int4   j4 = *(const int4*)  (ib + k0 + c4 * 4);
            float4 w4 = *(const float4*)(wb + k0 + c4 * 4);
            const float* Ur = Ub + (size_t)r * NN;
            Ust[c4*4+0][r] = Ur[j4.x]; Ust[c4*4+1][r] = Ur[j4.y];
            Ust[c4*4+2][r] = Ur[j4.z]; Ust[c4*4+3][r] = Ur[j4.w];
            const float* Sr = Sb + (size_t)r * NN;
            const int*   Mr = Mb + (size_t)r * NN;
            Ast[c4*4+0][r] = Sr[j4.x] * (float)Mr[j4.x] * w4.x;
            Ast[c4*4+1][r] = Sr[j4.y] * (float)Mr[j4.y] * w4.y;
            Ast[c4*4+2][r] = Sr[j4.z] * (float)Mr[j4.z] * w4.z;
            Ast[c4*4+3][r] = Sr[j4.w] * (float)Mr[j4.w] * w4.w;
        }
        __syncthreads();
        #pragma unroll 16
        for (int k = 0; k < 64; k++) {
            float a[4], bv[4];
            #pragma unroll
            for (int u = 0; u < 4; u++) a[u]  = Ust[k][ty * 4 + u];
            #pragma unroll
            for (int v = 0; v < 4; v++) bv[v] = Ast[k][tx * 4 + v];
            #pragma unroll
            for (int u = 0; u < 4; u++)
                #pragma unroll
                for (int v = 0; v < 4; v++) acc[u][v] += a[u] * bv[v];
        }
        __syncthreads();
    }
    #pragma unroll
    for (int u = 0; u < 4; u++) {
        int oc = h * 64 + ty * 4 + u;
        #pragma unroll
        for (int v = 0; v < 4; v++) {
            int ig = it + tx * 4 + v;
            size_t o = ((size_t)b * CDIM + oc) * NN + ig;
            float val = acc[u][v];
            val += fv[tx * 4 + v] * Ub[(size_t)(ty * 4 + u) * NN + ig];  // diag term
            if (pre != nullptr) val += pre[o];
            out[o] = val;
        }
    }
}

// (B,CDIM,NN) -> (B,NN,CDIM)
__global__ void transpose_kernel(const float* __restrict__ in, float* __restrict__ out) {
    __shared__ float t[32][33];
    int b = blockIdx.z;
    int c0 = blockIdx.y * 32, n0 = blockIdx.x * 32;
    int x = threadIdx.x, y = threadIdx.y;
    for (int yy = y; yy < 32; yy += 8)
        t[yy][x] = in[((size_t)b * CDIM + c0 + yy) * NN + n0 + x];
    __syncthreads();
    for (int yy = y; yy < 32; yy += 8)
        out[((size_t)b * NN + n0 + yy) * CDIM + c0 + x] = t[x][yy];
}

// gts[m,o] = relu(sum_c F[m,c]*W[o,c] + b[o]),  m = b*NN+n
__global__ __launch_bounds__(256) void gts_kernel(
        const float* __restrict__ F, const float* __restrict__ W,
        const float* __restrict__ bias, float* __restrict__ out) {
    int mt = blockIdx.y * 64, ntc = blockIdx.x * 64;
    __shared__ float Fst[64][65];
    __shared__ float Wst[64][65];
    int tid = threadIdx.x, ty = tid >> 4, tx = tid & 15;
    float acc[4][4] = {};
    for (int k0 = 0; k0 < CDIM; k0 += 64) {
        #pragma unroll
        for (int l = 0; l < 4; l++) {
            int idx = tid + l * 256; int r = idx >> 4, c4 = idx & 15;
            float4 f4 = *(const float4*)(F + (size_t)(mt + r) * CDIM + k0 + c4 * 4);
            Fst[c4*4+0][r] = f4.x; Fst[c4*4+1][r] = f4.y; Fst[c4*4+2][r] = f4.z; Fst[c4*4+3][r] = f4.w;
            float4 w4 = *(const float4*)(W + (size_t)(ntc + r) * CDIM + k0 + c4 * 4);
            Wst[c4*4+0][r] = w4.x; Wst[c4*4+1][r] = w4.y; Wst[c4*4+2][r] = w4.z; Wst[c4*4+3][r] = w4.w;
        }
        __syncthreads();
        #pragma unroll 16
        for (int k = 0; k < 64; k++) {
            float a[4], bv[4];
            #pragma unroll
            for (int u = 0; u < 4; u++) a[u]  = Fst[k][ty * 4 + u];
            #pragma unroll
            for (int v = 0; v < 4; v++) bv[v] = Wst[k][tx * 4 + v];
            #pragma unroll
            for (int u = 0; u < 4; u++)
                #pragma unroll
                for (int v = 0; v < 4; v++) acc[u][v] += a[u] * bv[v];
        }
        __syncthreads();
    }
    #pragma unroll
    for (int u = 0; u < 4; u++)
        #pragma unroll
        for (int v = 0; v < 4; v++) {
            int oc = ntc + tx * 4 + v;
            float val = fmaxf(acc[u][v] + bias[oc], 0.0f);
            out[(size_t)(mt + ty * 4 + u) * CDIM + oc] = val;
        }
}

// LayerNorm over channels of y[b,n,c] = o2m[b,c,n]; writes node_feat and out0.
__global__ void final_kernel(const float* __restrict__ o2m,
                             const float* __restrict__ out2pre,
                             const float* __restrict__ lnw, const float* __restrict__ lnb,
                             float* __restrict__ out0, float* __restrict__ outnf) {
    int b = blockIdx.y, n = blockIdx.x;
    int c = threadIdx.x;
    float y = o2m[((size_t)b * CDIM + c) * NN + n];
    __shared__ float s1[256], s2[256];
    s1[c] = y; s2[c] = y * y;
    __syncthreads();
    for (int st = 128; st; st >>= 1) {
        if (c < st) { s1[c] += s1[c + st]; s2[c] += s2[c + st]; }
        __syncthreads();
    }
    float mu  = s1[0] * (1.0f / CDIM);
    float var = s2[0] * (1.0f / CDIM) - mu * mu;
    float rstd = rsqrtf(fmaxf(var, 0.0f) + 1e-6f);
    float nf = (y - mu) * rstd * lnw[c] + lnb[c];
    size_t oidx = ((size_t)b * NN + n) * CDIM + c;
    outnf[oidx] = nf;
    out0[oidx]  = out2pre[((size_t)b * CDIM + c) * NN + n] + nf;
}

// ---------------- launcher ----------------
extern "C" void kernel_launch(void* const* d_in, const int* in_sizes, int n_in,
                              void* d_out, int out_size) {
    (void)in_sizes; (void)n_in; (void)out_size;
    const float* input   = (const float*)d_in[0];
    const int*   mroi    = (const int*)  d_in[1];
    const int*   smask   = (const int*)  d_in[2];
    const float* gt_feat = (const float*)d_in[3];
    const float* w1      = (const float*)d_in[4];
    const float* b1      = (const float*)d_in[5];
    const float* w2      = (const float*)d_in[6];
    const float* b2      = (const float*)d_in[7];
    const float* gt_w    = (const float*)d_in[8];
    const float* gt_b    = (const float*)d_in[9];
    const float* lnw     = (const float*)d_in[10];
    const float* lnb     = (const float*)d_in[11];

    float* out0    = (float*)d_out;                           // out2.T (B,NN,C)
    float* out_gts = out0 + (size_t)BB * NN * CDIM;           // gts
    float* out_nf  = out0 + 2 * (size_t)BB * NN * CDIM;       // node_feat

    float *S, *vec, *cwc, *fmv, *pre, *out1, *o1T, *o2m;
    int *okm, *allok, *idxc, *cntp;
    cudaGetSymbolAddress((void**)&S,     g_S);
    cudaGetSymbolAddress((void**)&okm,   g_ok);
    cudaGetSymbolAddress((void**)&allok, g_allok);
    cudaGetSymbolAddress((void**)&vec,   g_vec);
    cudaGetSymbolAddress((void**)&idxc,  g_idxc);
    cudaGetSymbolAddress((void**)&cwc,   g_cwc);
    cudaGetSymbolAddress((void**)&cntp,  g_cntp);
    cudaGetSymbolAddress((void**)&fmv,   g_fmv);
    cudaGetSymbolAddress((void**)&pre,   g_pre);
    cudaGetSymbolAddress((void**)&out1,  g_out1);
    cudaGetSymbolAddress((void**)&o1T,   g_o1T);
    cudaGetSymbolAddress((void**)&o2m,   g_o2m);

    // #0 independent gts branch
    gts_kernel<<<dim3(CDIM / 64, (BB * NN) / 64), 256>>>(gt_feat, gt_w, gt_b, out_gts);
    // #1 gconv1 (independent of attention)
    gconv_kernel<<<dim3(NN / 64, GG, BB), 256>>>(input, w1, b1, pre);
    // #2 cos GEMM (zeroes okmask)
    cos_gemm_sym_kernel<<<dim3(136, BH), 256>>>(input, S, okm);
    // #3 exact diag-domination counts
    diagcheck_kernel<<<(BH * NN) / 8, 256>>>(S, okm);
    // #4 vec + allok
    vecfinal_kernel<<<1, NN>>>(okm, vec, allok);
    // #5 exact fallback (early-exits when allok)
    topk_kernel<<<(BH * NN) / 8, 256>>>(S, vec, allok);
    // #6 column compaction + fmv
    compact_kernel<<<BB, NN>>>(smask, vec, idxc, cwc, cntp, fmv);
    // #7 compacted fused mask + message GEMM: out1 = pre + msg
    ogemm_fused_kernel<<<dim3(NN / 64, BH), 256>>>(pre, S, mroi, idxc, cwc, cntp, fmv, pre, out1);
    // #8 transpose to node-major
    transpose_kernel<<<dim3(NN / 32, CDIM / 32, BB), dim3(32, 8)>>>(out1, o1T);

    // ---- stage 2 ----
    cos_gemm_sym_kernel<<<dim3(136, BH), 256>>>(o1T, S, okm);
    diagcheck_kernel<<<(BH * NN) / 8, 256>>>(S, okm);
    vecfinal_kernel<<<1, NN>>>(okm, vec, allok);
    topk_kernel<<<(BH * NN) / 8, 256>>>(S, vec, allok);
    compact_kernel<<<BB, NN>>>(smask, vec, idxc, cwc, cntp, fmv);
    gconv_kernel<<<dim3(NN / 64, GG, BB), 256>>>(o1T, w2, b2, pre);      // out2_pre
    ogemm_fused_kernel<<<dim3(NN / 64, BH), 256>>>(pre, S, mroi, idxc, cwc, cntp, fmv, nullptr, o2m);
    final_kernel<<<dim3(NN, BB), 256>>>(o2m, pre, lnw, lnb, out0, out_nf);
}

// round 11
// speedup vs baseline: 1.3375x; 1.0348x over previous
#include <cuda_runtime.h>
#include <math.h>

#define BB   4
#define NN   1024
#define CDIM 256
#define HH   4
#define DKK  64
#define GG   4
#define BH   (BB*HH)

// ---------------- scratch (device globals; no allocation) ----------------
__device__ float g_S    [(size_t)BH * NN * NN];  // raw cosine-relu matrix [bh][i][j]
__device__ int   g_cnt  [(size_t)BH * NN];       // per-(bh,i) domination counters
__device__ int   g_allok;                        // 1 if vec == all-ones exactly
__device__ float g_vec  [NN];                    // top-k union mask
__device__ int   g_idxc [(size_t)BB * NN];       // compacted surviving-column indices
__device__ float g_cwc  [(size_t)BB * NN];       // compacted column weights
__device__ int   g_cntp [BB];                    // padded compacted count per batch
__device__ int   g_cntr [BB];                    // real compacted count per batch
__device__ float g_fmv  [(size_t)BB * NN];       // 0.25*(sm[b,i]==0)
__device__ float g_pre  [(size_t)BB * CDIM * NN];// gconv output (stage1/2)
__device__ float g_out1 [(size_t)BB * CDIM * NN];// stage1 result (B,C,n)
__device__ float g_o1T  [(size_t)BB * NN * CDIM];// stage1 result (B,n,C)
__device__ float g_o2m  [(size_t)BB * CDIM * NN];// stage2 message

// ---------------- kernels ----------------

// Symmetric cosine GEMM with fused top-4 domination counting.
// Computes only lower-tri tiles (jt>=it), mirror-writes the transpose.
// For every stored element, counts (per row) entries preceding the diagonal in
// jax.lax.top_k order; d_i reproduced bitwise locally (norm chain == diag chain).
__global__ __launch_bounds__(256) void cos_gemm_sym_kernel(
        const float* __restrict__ X, float* __restrict__ S, int* __restrict__ cnt) {
    int bh = blockIdx.y, b = bh >> 2, h = bh & 3;
    int t = blockIdx.x;               // 0..135 tri-tile index
    int tr = (int)((sqrtf(8.0f * (float)t + 1.0f) - 1.0f) * 0.5f);
    while ((tr + 1) * (tr + 2) / 2 <= t) tr++;
    while (tr * (tr + 1) / 2 > t) tr--;
    int tc = t - tr * (tr + 1) / 2;   // tc <= tr
    int it = tc * 64, jt = tr * 64;   // jt >= it

    __shared__ float sbuf[2 * 64 * 65];           // A | B ; reused as transpose stage
    __shared__ float ssA[64], ssB[64];            // sum-of-squares per row
    __shared__ int   cA[64], cB[64];              // per-row partial counts
    #define AST(k,m) sbuf[(k)*65 + (m)]
    #define BST(k,n) sbuf[4160 + (k)*65 + (n)]
    int tid = threadIdx.x;
    if (tid < 64) { cA[tid] = 0; cB[tid] = 0; }
    const float* Abase = X + ((size_t)(b * NN + it)) * CDIM + h * DKK;
    const float* Bbase = X + ((size_t)(b * NN + jt)) * CDIM + h * DKK;
    #pragma unroll
    for (int l = 0; l < 4; l++) {
        int idx = tid + l * 256;
        int rr = idx >> 4, c4 = idx & 15;
        float4 va = *(const float4*)(Abase + (size_t)rr * CDIM + c4 * 4);
        float4 vb = *(const float4*)(Bbase + (size_t)rr * CDIM + c4 * 4);
        AST(c4*4+0, rr) = va.x; AST(c4*4+1, rr) = va.y; AST(c4*4+2, rr) = va.z; AST(c4*4+3, rr) = va.w;
        BST(c4*4+0, rr) = vb.x; BST(c4*4+1, rr) = vb.y; BST(c4*4+2, rr) = vb.z; BST(c4*4+3, rr) = vb.w;
    }
    __syncthreads();
    // in-tile sum of squares (same FFMA chain as the micro-loop diagonal)
    if (tid < 64) {
        float s = 0.0f;
        #pragma unroll 16
        for (int k = 0; k < DKK; k++) { float v = AST(k, tid); s += v * v; }
        ssA[tid] = s;
    } else if (tid < 128) {
        int n = tid - 64;
        float s = 0.0f;
        #pragma unroll 16
        for (int k = 0; k < DKK; k++) { float v = BST(k, n); s += v * v; }
        ssB[n] = s;
    }
    int ty = tid >> 4, tx = tid & 15;
    float acc[4][4] = {};
    #pragma unroll 16
    for (int k = 0; k < DKK; k++) {
        float a[4], bv[4];
        #pragma unroll
        for (int u = 0; u < 4; u++) a[u]  = AST(k, ty * 4 + u);
        #pragma unroll
        for (int v = 0; v < 4; v++) bv[v] = BST(k, tx * 4 + v);
        #pragma unroll
        for (int u = 0; u < 4; u++)
            #pragma unroll
            for (int v = 0; v < 4; v++) acc[u][v] += a[u] * bv[v];
    }
    __syncthreads();                               // ssA/ssB ready
    float ni[4], nj[4], dA[4], dB[4];
    #pragma unroll
    for (int u = 0; u < 4; u++) {
        float s = ssA[ty * 4 + u]; ni[u] = sqrtf(s);
        dA[u] = fmaxf(s / fmaxf(ni[u] * ni[u], 1e-8f), 0.0f);
    }
    #pragma unroll
    for (int v = 0; v < 4; v++) {
        float s = ssB[tx * 4 + v]; nj[v] = sqrtf(s);
        dB[v] = fmaxf(s / fmaxf(nj[v] * nj[v], 1e-8f), 0.0f);
    }
    float* Sout = S + (size_t)bh * NN * NN;
    float sv[4][4];
    int myA[4] = {0,0,0,0}, myB[4] = {0,0,0,0};
    #pragma unroll
    for (int u = 0; u < 4; u++)
        #pragma unroll
        for (int v = 0; v < 4; v++) {
            float d = fmaxf(ni[u] * nj[v], 1e-8f);
            float x = fmaxf(acc[u][v] / d, 0.0f);
            sv[u][v] = x;
            Sout[(size_t)(it + ty * 4 + u) * NN + jt + tx * 4 + v] = x;
            int gi = it + ty * 4 + u, gj = jt + tx * 4 + v;
            myA[u] += (x > dA[u] || (x == dA[u] && gj < gi));
            if (it != jt) myB[v] += (x > dB[v] || (x == dB[v] && gi < gj));
        }
    #pragma unroll
    for (int u = 0; u < 4; u++) if (myA[u]) atomicAdd(&cA[ty * 4 + u], myA[u]);
    if (it != jt) {
        #pragma unroll
        for (int v = 0; v < 4; v++) if (myB[v]) atomicAdd(&cB[tx * 4 + v], myB[v]);
    }
    __syncthreads();
    if (tid < 64) {
        if (cA[tid]) atomicAdd(&cnt[(size_t)bh * NN + it + tid], cA[tid]);
        if (it != jt && cB[tid]) atomicAdd(&cnt[(size_t)bh * NN + jt + tid], cB[tid]);
    }
    if (it != jt) {
        float* T = sbuf;                           // 64 x 68 stage
        #pragma unroll
        for (int u = 0; u < 4; u++)
            #pragma unroll
            for (int v = 0; v < 4; v++)
                T[(tx * 4 + v) * 68 + ty * 4 + u] = sv[u][v];
        __syncthreads();
        #pragma unroll
        for (int l = 0; l < 4; l++) {
            int idx = tid + l * 256;
            int rr = idx >> 4, c4 = idx & 15;
            float4 o = *(const float4*)&T[rr * 68 + c4 * 4];
            *(float4*)&Sout[(size_t)(jt + rr) * NN + it + c4 * 4] = o;
        }
    }
    #undef AST
    #undef BST
}

// zero the counters (once, before stage 1; okfinal re-zeroes for stage 2)
__global__ void zerocnt_kernel(int* __restrict__ cnt) {
    cnt[(size_t)blockIdx.x * NN + threadIdx.x] = 0;
}

// vec[i] = OR_bh (cnt[bh,i] < 4); allok = AND_i vec; re-zeroes cnt. One block 1024.
__global__ void okfinal_kernel(int* __restrict__ cnt,
                               float* __restrict__ vec, int* __restrict__ allok) {
    int i = threadIdx.x;
    int ok = 0;
    #pragma unroll
    for (int bh = 0; bh < BH; bh++) {
        size_t q = (size_t)bh * NN + i;
        if (cnt[q] < 4) ok = 1;
        cnt[q] = 0;
    }
    vec[i] = ok ? 1.0f : 0.0f;
    int all = __syncthreads_and(ok);
    if (i == 0) *allok = all ? 1 : 0;
}

// Fallback exact top-4 union; early-exits when diag-domination proved vec==1.
__global__ void topk_kernel(const float* __restrict__ S, float* __restrict__ vec,
                            const int* __restrict__ allok) {
    if (*allok) return;
    int row  = blockIdx.x * (blockDim.x >> 5) + (threadIdx.x >> 5);
    int lane = threadIdx.x & 31;
    if (row >= BH * NN) return;
    const float* p = S + (size_t)row * NN;
    float v[4] = {-1e30f, -1e30f, -1e30f, -1e30f};
    int   id[4] = {0, 0, 0, 0};
    for (int j = lane; j < NN; j += 32) {
        float x = p[j];
        if (x > v[3]) {
            if (x > v[0])      { v[3]=v[2];id[3]=id[2]; v[2]=v[1];id[2]=id[1]; v[1]=v[0];id[1]=id[0]; v[0]=x; id[0]=j; }
            else if (x > v[1]) { v[3]=v[2];id[3]=id[2]; v[2]=v[1];id[2]=id[1]; v[1]=x; id[1]=j; }
            else if (x > v[2]) { v[3]=v[2];id[3]=id[2]; v[2]=x; id[2]=j; }
            else               { v[3]=x; id[3]=j; }
        }
    }
    #pragma unroll
    for (int r = 0; r < 4; r++) {
        float best = v[0]; int bl = lane;
        #pragma unroll
        for (int off = 16; off; off >>= 1) {
            float ov = __shfl_xor_sync(0xffffffffu, best, off);
            int   ol = __shfl_xor_sync(0xffffffffu, bl, off);
            if (ov > best || (ov == best && ol < bl)) { best = ov; bl = ol; }
        }
        int widx = __shfl_sync(0xffffffffu, id[0], bl);
        if (lane == 0) vec[widx] = 1.0f;
        if (lane == bl) { v[0]=v[1];id[0]=id[1]; v[1]=v[2];id[1]=id[2]; v[2]=v[3];id[2]=id[3]; v[3]=-1e30f; }
    }
}

// Per-batch compaction of surviving columns (sm[b,j]!=0), order-preserving.
// Depends only on smask -> run ONCE. idx padded to mult of 64 with 0.
// Also writes fmv[b,i] = 0.25*(sm==0). One block of 1024 per batch.
__global__ void compact_kernel(const int* __restrict__ smask,
                               int* __restrict__ idxc, int* __restrict__ cntp,
                               int* __restrict__ cntr, float* __restrict__ fmv) {
    int b = blockIdx.x, j = threadIdx.x;
    __shared__ int ps[NN];
    int s = (smask[(size_t)b * NN + j] != 0) ? 1 : 0;
    ps[j] = s;
    __syncthreads();
    for (int off = 1; off < NN; off <<= 1) {
        int v = (j >= off) ? ps[j - off] : 0;
        __syncthreads();
        ps[j] += v;
        __syncthreads();
    }
    int total = ps[NN - 1];
    if (s) idxc[(size_t)b * NN + (ps[j] - 1)] = j;
    int padded = (total + 63) & ~63;
    for (int p = total + j; p < padded; p += NN) idxc[(size_t)b * NN + p] = 0;
    if (j == 0) { cntp[b] = padded; cntr[b] = total; }
    fmv[(size_t)b * NN + j] = s ? 0.0f : 0.25f;
}

// cwc[b,p] = 0.25*vec[idx[p]] for p<real, else 0. One block 1024 per batch.
__global__ void cwcfill_kernel(const int* __restrict__ idxc, const int* __restrict__ cntr,
                               const float* __restrict__ vec, float* __restrict__ cwc) {
    int b = blockIdx.x, p = threadIdx.x;
    int real = cntr[b];
    cwc[(size_t)b * NN + p] = (p < real) ? 0.25f * vec[idxc[(size_t)b * NN + p]] : 0.0f;
}

// grouped 1x1 conv + relu. Xin node-major (B,NN,CDIM); out (B,CDIM,NN).
__global__ __launch_bounds__(256) void gconv_kernel(
        const float* __restrict__ Xin, const float* __restrict__ W,
        const float* __restrict__ bias, float* __restrict__ out) {
    int b = blockIdx.z, g = blockIdx.y, nt = blockIdx.x * 64;
    __shared__ float Wst[64][65];    // [ci][o]
    __shared__ float Xst[64][65];    // [ci][n]
    int tid = threadIdx.x;
    const float* Wb = W + (size_t)g * 64 * 64;
    const float* Xb = Xin + ((size_t)b * NN + nt) * CDIM + g * 64;
    #pragma unroll
    for (int l = 0; l < 4; l++) {
        int idx = tid + l * 256; int r = idx >> 4, c4 = idx & 15;
        float4 w4 = *(const float4*)(Wb + (size_t)r * 64 + c4 * 4);
        Wst[c4*4+0][r] = w4.x; Wst[c4*4+1][r] = w4.y; Wst[c4*4+2][r] = w4.z; Wst[c4*4+3][r] = w4.w;
        float4 x4 = *(const float4*)(Xb + (size_t)r * CDIM + c4 * 4);
        Xst[c4*4+0][r] = x4.x; Xst[c4*4+1][r] = x4.y; Xst[c4*4+2][r] = x4.z; Xst[c4*4+3][r] = x4.w;
    }
    __syncthreads();
    int ty = tid >> 4, tx = tid & 15;
    float acc[4][4] = {};
    #pragma unroll 16
    for (int k = 0; k < 64; k++) {
        float a[4], bv[4];
        #pragma unroll
        for (int u = 0; u < 4; u++) a[u]  = Wst[k][ty * 4 + u];
        #pragma unroll
        for (int v = 0; v < 4; v++) bv[v] = Xst[k][tx * 4 + v];
        #pragma unroll
        for (int u = 0; u < 4; u++)
            #pragma unroll
            for (int v = 0; v < 4; v++) acc[u][v] += a[u] * bv[v];
    }
    #pragma unroll
    for (int u = 0; u < 4; u++) {
        int oc = g * 64 + ty * 4 + u;
        float bs = bias[oc];
        #pragma unroll
        for (int v = 0; v < 4; v++) {
            float val = fmaxf(acc[u][v] + bs, 0.0f);
            out[((size_t)b * CDIM + oc) * NN + nt + tx * 4 + v] = val;
        }
    }
}

// Compacted fused message GEMM, k over surviving columns only:
// o[b,h*64+cc,i] = sum_{p<cnt} U[cc, idx[p]] * S[i,idx[p]]*mroi[i,idx[p]]*cwc[p]
//                  + fmv[i]*U[cc,i]  (+ pre if given)
__global__ __launch_bounds__(256) void ogemm_fused_kernel(
        const float* __restrict__ U, const float* __restrict__ S,
        const int* __restrict__ mroi,
        const int* __restrict__ idxc, const float* __restrict__ cwc,
        const int* __restrict__ cntp, const float* __restrict__ fmv,
        const float* __restrict__ pre, float* __restrict__ out) {
    int bh = blockIdx.y, b = bh >> 2, h = bh & 3;
    int it = blockIdx.x * 64;
    __shared__ float Ust[64][65];    // [k][cc]
    __shared__ float Ast[64][65];    // [k][i]
    const float* Ub = U  + ((size_t)b * CDIM + h * 64) * NN;
    const float* Sb = S  + ((size_t)bh * NN + it) * NN;
    const int*   Mb = mroi + ((size_t)b * NN + it) * NN;
    const int*   ib = idxc + (size_t)b * NN;
    const float* wb = cwc  + (size_t)b * NN;
    const float* fv = fmv  + (size_t)b * NN + it;
    int cnt = cntp[b];
    int tid = threadIdx.x, ty = tid >> 4, tx = tid & 15;
    float acc[4][4] = {};
    for (int k0 = 0; k0 < cnt; k0 += 64) {
        #pragma unroll
        for (int l = 0; l < 4; l++) {
            int idx = tid + l * 256; int r = idx >> 4, c4 = idx & 15;
            int4   j4 = *(const int4*)  (ib + k0 + c4 * 4);
            float4 w4 = *(const float4*)(wb + k0 + c4 * 4);
            const float* Ur = Ub + (size_t)r * NN;
            Ust[c4*4+0][r] = Ur[j4.x]; Ust[c4*4+1][r] = Ur[j4.y];
            Ust[c4*4+2][r] = Ur[j4.z]; Ust[c4*4+3][r] = Ur[j4.w];
            const float* Sr = Sb + (size_t)r * NN;
            const int*   Mr = Mb + (size_t)r * NN;
            Ast[c4*4+0][r] = Sr[j4.x] * (float)Mr[j4.x] * w4.x;
            Ast[c4*4+1][r] = Sr[j4.y] * (float)Mr[j4.y] * w4.y;
            Ast[c4*4+2][r] = Sr[j4.z] * (float)Mr[j4.z] * w4.z;
            Ast[c4*4+3][r] = Sr[j4.w] * (float)Mr[j4.w] * w4.w;
        }
        __syncthreads();
        #pragma unroll 16
        for (int k = 0; k < 64; k++) {
            float a[4], bv[4];
            #pragma unroll
            for (int u = 0; u < 4; u++) a[u]  = Ust[k][ty * 4 + u];
            #pragma unroll
            for (int v = 0; v < 4; v++) bv[v] = Ast[k][tx * 4 + v];
            #pragma unroll
            for (int u = 0; u < 4; u++)
                #pragma unroll
                for (int v = 0; v < 4; v++) acc[u][v] += a[u] * bv[v];
        }
        __syncthreads();
    }
    #pragma unroll
    for (int u = 0; u < 4; u++) {
        int oc = h * 64 + ty * 4 + u;
        #pragma unroll
        for (int v = 0; v < 4; v++) {
            int ig = it + tx * 4 + v;
            size_t o = ((size_t)b * CDIM + oc) * NN + ig;
            float val = acc[u][v];
            val += fv[tx * 4 + v] * Ub[(size_t)(ty * 4 + u) * NN + ig];  // diag term
            if (pre != nullptr) val += pre[o];
            out[o] = val;
        }
    }
}

// (B,CDIM,NN) -> (B,NN,CDIM)
__global__ void transpose_kernel(const float* __restrict__ in, float* __restrict__ out) {
    __shared__ float t[32][33];
    int b = blockIdx.z;
    int c0 = blockIdx.y * 32, n0 = blockIdx.x * 32;
    int x = threadIdx.x, y = threadIdx.y;
    for (int yy = y; yy < 32; yy += 8)
        t[yy][x] = in[((size_t)b * CDIM + c0 + yy) * NN + n0 + x];
    __syncthreads();
    for (int yy = y; yy < 32; yy += 8)
        out[((size_t)b * NN + n0 + yy) * CDIM + c0 + x] = t[x][yy];
}

// gts[m,o] = relu(sum_c F[m,c]*W[o,c] + b[o]),  m = b*NN+n
__global__ __launch_bounds__(256) void gts_kernel(
        const float* __restrict__ F, const float* __restrict__ W,
        const float* __restrict__ bias, float* __restrict__ out) {
    int mt = blockIdx.y * 64, ntc = blockIdx.x * 64;
    __shared__ float Fst[64][65];
    __shared__ float Wst[64][65];
    int tid = threadIdx.x, ty = tid >> 4, tx = tid & 15;
    float acc[4][4] = {};
    for (int k0 = 0; k0 < CDIM; k0 += 64) {
        #pragma unroll
        for (int l = 0; l < 4; l++) {
            int idx = tid + l * 256; int r = idx >> 4, c4 = idx & 15;
            float4 f4 = *(const float4*)(F + (size_t)(mt + r) * CDIM + k0 + c4 * 4);
            Fst[c4*4+0][r] = f4.x; Fst[c4*4+1][r] = f4.y; Fst[c4*4+2][r] = f4.z; Fst[c4*4+3][r] = f4.w;
            float4 w4 = *(const float4*)(W + (size_t)(ntc + r) * CDIM + k0 + c4 * 4);
            Wst[c4*4+0][r] = w4.x; Wst[c4*4+1][r] = w4.y; Wst[c4*4+2][r] = w4.z; Wst[c4*4+3][r] = w4.w;
        }
        __syncthreads();
        #pragma unroll 16
        for (int k = 0; k < 64; k++) {
            float a[4], bv[4];
            #pragma unroll
            for (int u = 0; u < 4; u++) a[u]  = Fst[k][ty * 4 + u];
            #pragma unroll
            for (int v = 0; v < 4; v++) bv[v] = Wst[k][tx * 4 + v];
            #pragma unroll
            for (int u = 0; u < 4; u++)
                #pragma unroll
                for (int v = 0; v < 4; v++) acc[u][v] += a[u] * bv[v];
        }
        __syncthreads();
    }
    #pragma unroll
    for (int u = 0; u < 4; u++)
        #pragma unroll
        for (int v = 0; v < 4; v++) {
            int oc = ntc + tx * 4 + v;
            float val = fmaxf(acc[u][v] + bias[oc], 0.0f);
            out[(size_t)(mt + ty * 4 + u) * CDIM + oc] = val;
        }
}

// LayerNorm over channels of y[b,n,c] = o2m[b,c,n]; writes node_feat and out0.
__global__ void final_kernel(const float* __restrict__ o2m,
                             const float* __restrict__ out2pre,
                             const float* __restrict__ lnw, const float* __restrict__ lnb,
                             float* __restrict__ out0, float* __restrict__ outnf) {
    int b = blockIdx.y, n = blockIdx.x;
    int c = threadIdx.x;
    float y = o2m[((size_t)b * CDIM + c) * NN + n];
    __shared__ float s1[256], s2[256];
    s1[c] = y; s2[c] = y * y;
    __syncthreads();
    for (int st = 128; st; st >>= 1) {
        if (c < st) { s1[c] += s1[c + st]; s2[c] += s2[c + st]; }
        __syncthreads();
    }
    float mu  = s1[0] * (1.0f / CDIM);
    float var = s2[0] * (1.0f / CDIM) - mu * mu;
    float rstd = rsqrtf(fmaxf(var, 0.0f) + 1e-6f);
    float nf = (y - mu) * rstd * lnw[c] + lnb[c];
    size_t oidx = ((size_t)b * NN + n) * CDIM + c;
    outnf[oidx] = nf;
    out0[oidx]  = out2pre[((size_t)b * CDIM + c) * NN + n] + nf;
}

// ---------------- launcher ----------------
extern "C" void kernel_launch(void* const* d_in, const int* in_sizes, int n_in,
                              void* d_out, int out_size) {
    (void)in_sizes; (void)n_in; (void)out_size;
    const float* input   = (const float*)d_in[0];
    const int*   mroi    = (const int*)  d_in[1];
    const int*   smask   = (const int*)  d_in[2];
    const float* gt_feat = (const float*)d_in[3];
    const float* w1      = (const float*)d_in[4];
    const float* b1      = (const float*)d_in[5];
    const float* w2      = (const float*)d_in[6];
    const float* b2      = (const float*)d_in[7];
    const float* gt_w    = (const float*)d_in[8];
    const float* gt_b    = (const float*)d_in[9];
    const float* lnw     = (const float*)d_in[10];
    const float* lnb     = (const float*)d_in[11];

    float* out0    = (float*)d_out;                           // out2.T (B,NN,C)
    float* out_gts = out0 + (size_t)BB * NN * CDIM;           // gts
    float* out_nf  = out0 + 2 * (size_t)BB * NN * CDIM;       // node_feat

    float *S, *vec, *cwc, *fmv, *pre, *out1, *o1T, *o2m;
    int *cntarr, *allok, *idxc, *cntp, *cntr;
    cudaGetSymbolAddress((void**)&S,      g_S);
    cudaGetSymbolAddress((void**)&cntarr, g_cnt);
    cudaGetSymbolAddress((void**)&allok,  g_allok);
    cudaGetSymbolAddress((void**)&vec,    g_vec);
    cudaGetSymbolAddress((void**)&idxc,   g_idxc);
    cudaGetSymbolAddress((void**)&cwc,    g_cwc);
    cudaGetSymbolAddress((void**)&cntp,   g_cntp);
    cudaGetSymbolAddress((void**)&cntr,   g_cntr);
    cudaGetSymbolAddress((void**)&fmv,    g_fmv);
    cudaGetSymbolAddress((void**)&pre,    g_pre);
    cudaGetSymbolAddress((void**)&out1,   g_out1);
    cudaGetSymbolAddress((void**)&o1T,    g_o1T);
    cudaGetSymbolAddress((void**)&o2m,    g_o2m);

    // independent prep
    gts_kernel<<<dim3(CDIM / 64, (BB * NN) / 64), 256>>>(gt_feat, gt_w, gt_b, out_gts);
    compact_kernel<<<BB, NN>>>(smask, idxc, cntp, cntr, fmv);
    zerocnt_kernel<<<BH, NN>>>(cntarr);
    gconv_kernel<<<dim3(NN / 64, GG, BB), 256>>>(input, w1, b1, pre);

    // ---- stage 1 ----
    cos_gemm_sym_kernel<<<dim3(136, BH), 256>>>(input, S, cntarr);
    okfinal_kernel<<<1, NN>>>(cntarr, vec, allok);            // also re-zeroes cnt
    topk_kernel<<<(BH * NN) / 8, 256>>>(S, vec, allok);       // exact fallback
    cwcfill_kernel<<<BB, NN>>>(idxc, cntr, vec, cwc);
    ogemm_fused_kernel<<<dim3(NN / 64, BH), 256>>>(pre, S, mroi, idxc, cwc, cntp, fmv, pre, out1);
    transpose_kernel<<<dim3(NN / 32, CDIM / 32, BB), dim3(32, 8)>>>(out1, o1T);

    // ---- stage 2 ----
    gconv_kernel<<<dim3(NN / 64, GG, BB), 256>>>(o1T, w2, b2, pre);      // out2_pre
    cos_gemm_sym_kernel<<<dim3(136, BH), 256>>>(o1T, S, cntarr);
    okfinal_kernel<<<1, NN>>>(cntarr, vec, allok);
    topk_kernel<<<(BH * NN) / 8, 256>>>(S, vec, allok);
    cwcfill_kernel<<<BB, NN>>>(idxc, cntr, vec, cwc);
    ogemm_fused_kernel<<<dim3(NN / 64, BH), 256>>>(pre, S, mroi, idxc, cwc, cntp, fmv, nullptr, o2m);
    final_kernel<<<dim3(NN, BB), 256>>>(o2m, pre, lnw, lnb, out0, out_nf);
}

// round 14
// speedup vs baseline: 1.3838x; 1.0346x over previous
#include <cuda_runtime.h>
#include <math.h>

#define BB   4
#define NN   1024
#define CDIM 256
#define HH   4
#define DKK  64
#define GG   4
#define BH   (BB*HH)

// ---------------- scratch (device globals; no allocation) ----------------
__device__ float g_S    [(size_t)BH * NN * NN];  // raw cosine-relu matrix [bh][i][j]
__device__ int   g_cnt  [(size_t)BH * NN];       // per-(bh,i) domination counters
__device__ int   g_allok;                        // 1 if vec == all-ones exactly
__device__ float g_vec  [NN];                    // top-k union mask
__device__ int   g_idxc [(size_t)BB * NN];       // compacted surviving-column indices
__device__ float g_cwc  [(size_t)BB * NN];       // compacted column weights
__device__ int   g_cntp [BB];                    // padded compacted count per batch
__device__ int   g_cntr [BB];                    // real compacted count per batch
__device__ float g_fmv  [(size_t)BB * NN];       // 0.25*(sm[b,i]==0)
__device__ float g_pre  [(size_t)BB * CDIM * NN];// gconv output (stage1/2)
__device__ float g_o1T  [(size_t)BB * NN * CDIM];// stage1 result (B,n,C)
__device__ float g_o2m  [(size_t)BB * CDIM * NN];// stage2 message

// ---------------- kernels ----------------

// Symmetric cosine GEMM with fused top-4 domination counting.
// Computes only lower-tri tiles (jt>=it), mirror-writes the transpose.
__global__ __launch_bounds__(256) void cos_gemm_sym_kernel(
        const float* __restrict__ X, float* __restrict__ S, int* __restrict__ cnt) {
    int bh = blockIdx.y, b = bh >> 2, h = bh & 3;
    int t = blockIdx.x;               // 0..135 tri-tile index
    int tr = (int)((sqrtf(8.0f * (float)t + 1.0f) - 1.0f) * 0.5f);
    while ((tr + 1) * (tr + 2) / 2 <= t) tr++;
    while (tr * (tr + 1) / 2 > t) tr--;
    int tc = t - tr * (tr + 1) / 2;   // tc <= tr
    int it = tc * 64, jt = tr * 64;   // jt >= it

    __shared__ float sbuf[2 * 64 * 65];           // A | B ; reused as transpose stage
    __shared__ float ssA[64], ssB[64];            // sum-of-squares per row
    __shared__ int   cA[64], cB[64];              // per-row partial counts
    #define AST(k,m) sbuf[(k)*65 + (m)]
    #define BST(k,n) sbuf[4160 + (k)*65 + (n)]
    int tid = threadIdx.x;
    if (tid < 64) { cA[tid] = 0; cB[tid] = 0; }
    const float* Abase = X + ((size_t)(b * NN + it)) * CDIM + h * DKK;
    const float* Bbase = X + ((size_t)(b * NN + jt)) * CDIM + h * DKK;
    #pragma unroll
    for (int l = 0; l < 4; l++) {
        int idx = tid + l * 256;
        int rr = idx >> 4, c4 = idx & 15;
        float4 va = *(const float4*)(Abase + (size_t)rr * CDIM + c4 * 4);
        float4 vb = *(const float4*)(Bbase + (size_t)rr * CDIM + c4 * 4);
        AST(c4*4+0, rr) = va.x; AST(c4*4+1, rr) = va.y; AST(c4*4+2, rr) = va.z; AST(c4*4+3, rr) = va.w;
        BST(c4*4+0, rr) = vb.x; BST(c4*4+1, rr) = vb.y; BST(c4*4+2, rr) = vb.z; BST(c4*4+3, rr) = vb.w;
    }
    __syncthreads();
    // in-tile sum of squares (same FFMA chain as the micro-loop diagonal)
    if (tid < 64) {
        float s = 0.0f;
        #pragma unroll 16
        for (int k = 0; k < DKK; k++) { float v = AST(k, tid); s += v * v; }
        ssA[tid] = s;
    } else if (tid < 128) {
        int n = tid - 64;
        float s = 0.0f;
        #pragma unroll 16
        for (int k = 0; k < DKK; k++) { float v = BST(k, n); s += v * v; }
        ssB[n] = s;
    }
    int ty = tid >> 4, tx = tid & 15;
    float acc[4][4] = {};
    #pragma unroll 16
    for (int k = 0; k < DKK; k++) {
        float a[4], bv[4];
        #pragma unroll
        for (int u = 0; u < 4; u++) a[u]  = AST(k, ty * 4 + u);
        #pragma unroll
        for (int v = 0; v < 4; v++) bv[v] = BST(k, tx * 4 + v);
        #pragma unroll
        for (int u = 0; u < 4; u++)
            #pragma unroll
            for (int v = 0; v < 4; v++) acc[u][v] += a[u] * bv[v];
    }
    __syncthreads();                               // ssA/ssB ready
    float ni[4], nj[4], dA[4], dB[4];
    #pragma unroll
    for (int u = 0; u < 4; u++) {
        float s = ssA[ty * 4 + u]; ni[u] = sqrtf(s);
        dA[u] = fmaxf(s / fmaxf(ni[u] * ni[u], 1e-8f), 0.0f);
    }
    #pragma unroll
    for (int v = 0; v < 4; v++) {
        float s = ssB[tx * 4 + v]; nj[v] = sqrtf(s);
        dB[v] = fmaxf(s / fmaxf(nj[v] * nj[v], 1e-8f), 0.0f);
    }
    float* Sout = S + (size_t)bh * NN * NN;
    float sv[4][4];
    int myA[4] = {0,0,0,0}, myB[4] = {0,0,0,0};
    #pragma unroll
    for (int u = 0; u < 4; u++)
        #pragma unroll
        for (int v = 0; v < 4; v++) {
            float d = fmaxf(ni[u] * nj[v], 1e-8f);
            float x = fmaxf(acc[u][v] / d, 0.0f);
            sv[u][v] = x;
            Sout[(size_t)(it + ty * 4 + u) * NN + jt + tx * 4 + v] = x;
            int gi = it + ty * 4 + u, gj = jt + tx * 4 + v;
            myA[u] += (x > dA[u] || (x == dA[u] && gj < gi));
            if (it != jt) myB[v] += (x > dB[v] || (x == dB[v] && gi < gj));
        }
    #pragma unroll
    for (int u = 0; u < 4; u++) if (myA[u]) atomicAdd(&cA[ty * 4 + u], myA[u]);
    if (it != jt) {
        #pragma unroll
        for (int v = 0; v < 4; v++) if (myB[v]) atomicAdd(&cB[tx * 4 + v], myB[v]);
    }
    __syncthreads();
    if (tid < 64) {
        if (cA[tid]) atomicAdd(&cnt[(size_t)bh * NN + it + tid], cA[tid]);
        if (it != jt && cB[tid]) atomicAdd(&cnt[(size_t)bh * NN + jt + tid], cB[tid]);
    }
    if (it != jt) {
        float* T = sbuf;                           // 64 x 68 stage
        #pragma unroll
        for (int u = 0; u < 4; u++)
            #pragma unroll
            for (int v = 0; v < 4; v++)
                T[(tx * 4 + v) * 68 + ty * 4 + u] = sv[u][v];
        __syncthreads();
        #pragma unroll
        for (int l = 0; l < 4; l++) {
            int idx = tid + l * 256;
            int rr = idx >> 4, c4 = idx & 15;
            float4 o = *(const float4*)&T[rr * 68 + c4 * 4];
            *(float4*)&Sout[(size_t)(jt + rr) * NN + it + c4 * 4] = o;
        }
    }
    #undef AST
    #undef BST
}

// vec[i] = OR_bh (cnt[bh,i] < 4); allok = AND_i vec; re-zeroes cnt. One block 1024.
__global__ void okfinal_kernel(int* __restrict__ cnt,
                               float* __restrict__ vec, int* __restrict__ allok) {
    int i = threadIdx.x;
    int ok = 0;
    #pragma unroll
    for (int bh = 0; bh < BH; bh++) {
        size_t q = (size_t)bh * NN + i;
        if (cnt[q] < 4) ok = 1;
        cnt[q] = 0;
    }
    vec[i] = ok ? 1.0f : 0.0f;
    int all = __syncthreads_and(ok);
    if (i == 0) *allok = all ? 1 : 0;
}

// Fallback exact top-4 union; early-exits when diag-domination proved vec==1.
__global__ void topk_kernel(const float* __restrict__ S, float* __restrict__ vec,
                            const int* __restrict__ allok) {
    if (*allok) return;
    int row  = blockIdx.x * (blockDim.x >> 5) + (threadIdx.x >> 5);
    int lane = threadIdx.x & 31;
    if (row >= BH * NN) return;
    const float* p = S + (size_t)row * NN;
    float v[4] = {-1e30f, -1e30f, -1e30f, -1e30f};
    int   id[4] = {0, 0, 0, 0};
    for (int j = lane; j < NN; j += 32) {
        float x = p[j];
        if (x > v[3]) {
            if (x > v[0])      { v[3]=v[2];id[3]=id[2]; v[2]=v[1];id[2]=id[1]; v[1]=v[0];id[1]=id[0]; v[0]=x; id[0]=j; }
            else if (x > v[1]) { v[3]=v[2];id[3]=id[2]; v[2]=v[1];id[2]=id[1]; v[1]=x; id[1]=j; }
            else if (x > v[2]) { v[3]=v[2];id[3]=id[2]; v[2]=x; id[2]=j; }
            else               { v[3]=x; id[3]=j; }
        }
    }
    #pragma unroll
    for (int r = 0; r < 4; r++) {
        float best = v[0]; int bl = lane;
        #pragma unroll
        for (int off = 16; off; off >>= 1) {
            float ov = __shfl_xor_sync(0xffffffffu, best, off);
            int   ol = __shfl_xor_sync(0xffffffffu, bl, off);
            if (ov > best || (ov == best && ol < bl)) { best = ov; bl = ol; }
        }
        int widx = __shfl_sync(0xffffffffu, id[0], bl);
        if (lane == 0) vec[widx] = 1.0f;
        if (lane == bl) { v[0]=v[1];id[0]=id[1]; v[1]=v[2];id[1]=id[2]; v[2]=v[3];id[2]=id[3]; v[3]=-1e30f; }
    }
}

// Per-batch compaction of surviving columns (sm[b,j]!=0), order-preserving.
// Depends only on smask -> run ONCE. idx padded to mult of 64 with 0.
// Also writes fmv[b,i] and zeroes this batch's 4 cnt rows-of-1024 (fused zerocnt).
__global__ void compact_kernel(const int* __restrict__ smask,
                               int* __restrict__ idxc, int* __restrict__ cntp,
                               int* __restrict__ cntr, float* __restrict__ fmv,
                               int* __restrict__ cnt) {
    int b = blockIdx.x, j = threadIdx.x;
    #pragma unroll
    for (int l = 0; l < 4; l++) cnt[(size_t)b * 4096 + l * 1024 + j] = 0;
    __shared__ int ps[NN];
    int s = (smask[(size_t)b * NN + j] != 0) ? 1 : 0;
    ps[j] = s;
    __syncthreads();
    for (int off = 1; off < NN; off <<= 1) {
        int v = (j >= off) ? ps[j - off] : 0;
        __syncthreads();
        ps[j] += v;
        __syncthreads();
    }
    int total = ps[NN - 1];
    if (s) idxc[(size_t)b * NN + (ps[j] - 1)] = j;
    int padded = (total + 63) & ~63;
    for (int p = total + j; p < padded; p += NN) idxc[(size_t)b * NN + p] = 0;
    if (j == 0) { cntp[b] = padded; cntr[b] = total; }
    fmv[(size_t)b * NN + j] = s ? 0.0f : 0.25f;
}

// cwc[b,p] = 0.25*vec[idx[p]] for p<real, else 0. One block 1024 per batch.
__global__ void cwcfill_kernel(const int* __restrict__ idxc, const int* __restrict__ cntr,
                               const float* __restrict__ vec, float* __restrict__ cwc) {
    int b = blockIdx.x, p = threadIdx.x;
    int real = cntr[b];
    cwc[(size_t)b * NN + p] = (p < real) ? 0.25f * vec[idxc[(size_t)b * NN + p]] : 0.0f;
}

// grouped 1x1 conv + relu, 64o x 32n tiles for occupancy (grid 512).
// Xin node-major (B,NN,CDIM); out (B,CDIM,NN).
__global__ __launch_bounds__(256) void gconv_kernel(
        const float* __restrict__ Xin, const float* __restrict__ W,
        const float* __restrict__ bias, float* __restrict__ out) {
    int b = blockIdx.z, g = blockIdx.y, nt = blockIdx.x * 32;
    __shared__ float Wst[64][65];    // [ci][o]
    __shared__ float Xst[64][33];    // [ci][n]
    int tid = threadIdx.x;
    const float* Wb = W + (size_t)g * 64 * 64;
    const float* Xb = Xin + ((size_t)b * NN + nt) * CDIM + g * 64;
    #pragma unroll
    for (int l = 0; l < 4; l++) {
        int idx = tid + l * 256; int r = idx >> 4, c4 = idx & 15;
        float4 w4 = *(const float4*)(Wb + (size_t)r * 64 + c4 * 4);
        Wst[c4*4+0][r] = w4.x; Wst[c4*4+1][r] = w4.y; Wst[c4*4+2][r] = w4.z; Wst[c4*4+3][r] = w4.w;
    }
    #pragma unroll
    for (int l = 0; l < 2; l++) {
        int idx = tid + l * 256; int r = idx >> 4, c4 = idx & 15;   // r 0..31
        float4 x4 = *(const float4*)(Xb + (size_t)r * CDIM + c4 * 4);
        Xst[c4*4+0][r] = x4.x; Xst[c4*4+1][r] = x4.y; Xst[c4*4+2][r] = x4.z; Xst[c4*4+3][r] = x4.w;
    }
    __syncthreads();
    int ty = tid >> 4, tx = tid & 15;
    float acc[4][2] = {};
    #pragma unroll 16
    for (int k = 0; k < 64; k++) {
        float a[4], bv[2];
        #pragma unroll
        for (int u = 0; u < 4; u++) a[u]  = Wst[k][ty * 4 + u];
        #pragma unroll
        for (int v = 0; v < 2; v++) bv[v] = Xst[k][tx * 2 + v];
        #pragma unroll
        for (int u = 0; u < 4; u++)
            #pragma unroll
            for (int v = 0; v < 2; v++) acc[u][v] += a[u] * bv[v];
    }
    #pragma unroll
    for (int u = 0; u < 4; u++) {
        int oc = g * 64 + ty * 4 + u;
        float bs = bias[oc];
        #pragma unroll
        for (int v = 0; v < 2; v++) {
            float val = fmaxf(acc[u][v] + bs, 0.0f);
            out[((size_t)b * CDIM + oc) * NN + nt + tx * 2 + v] = val;
        }
    }
}

// Compacted fused message GEMM, k over surviving columns only.
// If outT != null: write result TRANSPOSED to outT (B,n,C) via smem stage
// (eliminates the separate transpose kernel). Else write out (B,C,n).
__global__ __launch_bounds__(256) void ogemm_fused_kernel(
        const float* __restrict__ U, const float* __restrict__ S,
        const int* __restrict__ mroi,
        const int* __restrict__ idxc, const float* __restrict__ cwc,
        const int* __restrict__ cntp, const float* __restrict__ fmv,
        const float* __restrict__ pre, float* __restrict__ out,
        float* __restrict__ outT) {
    int bh = blockIdx.y, b = bh >> 2, h = bh & 3;
    int it = blockIdx.x * 64;
    __shared__ float smem[2 * 64 * 65];            // Ust | Ast ; reused as T stage
    float (*Ust)[65] = (float(*)[65])smem;         // [k][cc]
    float (*Ast)[65] = (float(*)[65])(smem + 4160);// [k][i]
    const float* Ub = U  + ((size_t)b * CDIM + h * 64) * NN;
    const float* Sb = S  + ((size_t)bh * NN + it) * NN;
    const int*   Mb = mroi + ((size_t)b * NN + it) * NN;
    const int*   ib = idxc + (size_t)b * NN;
    const float* wb = cwc  + (size_t)b * NN;
    const float* fv = fmv  + (size_t)b * NN + it;
    int cnt = cntp[b];
    int tid = threadIdx.x, ty = tid >> 4, tx = tid & 15;
    float acc[4][4] = {};
    for (int k0 = 0; k0 < cnt; k0 += 64) {
        #pragma unroll
        for (int l = 0; l < 4; l++) {
            int idx = tid + l * 256; int r = idx >> 4, c4 = idx & 15;
            int4   j4 = *(const int4*)  (ib + k0 + c4 * 4);
            float4 w4 = *(const float4*)(wb + k0 + c4 * 4);
            const float* Ur = Ub + (size_t)r * NN;
            Ust[c4*4+0][r] = Ur[j4.x]; Ust[c4*4+1][r] = Ur[j4.y];
            Ust[c4*4+2][r] = Ur[j4.z]; Ust[c4*4+3][r] = Ur[j4.w];
            const float* Sr = Sb + (size_t)r * NN;
            const int*   Mr = Mb + (size_t)r * NN;
            Ast[c4*4+0][r] = Sr[j4.x] * (float)Mr[j4.x] * w4.x;
            Ast[c4*4+1][r] = Sr[j4.y] * (float)Mr[j4.y] * w4.y;
            Ast[c4*4+2][r] = Sr[j4.z] * (float)Mr[j4.z] * w4.z;
            Ast[c4*4+3][r] = Sr[j4.w] * (float)Mr[j4.w] * w4.w;
        }
        __syncthreads();
        #pragma unroll 16
        for (int k = 0; k < 64; k++) {
            float a[4], bv[4];
            #pragma unroll
            for (int u = 0; u < 4; u++) a[u]  = Ust[k][ty * 4 + u];
            #pragma unroll
            for (int v = 0; v < 4; v++) bv[v] = Ast[k][tx * 4 + v];
            #pragma unroll
            for (int u = 0; u < 4; u++)
                #pragma unroll
                for (int v = 0; v < 4; v++) acc[u][v] += a[u] * bv[v];
        }
        __syncthreads();
    }
    if (outT == nullptr) {
        #pragma unroll
        for (int u = 0; u < 4; u++) {
            int oc = h * 64 + ty * 4 + u;
            #pragma unroll
            for (int v = 0; v < 4; v++) {
                int ig = it + tx * 4 + v;
                size_t o = ((size_t)b * CDIM + oc) * NN + ig;
                float val = acc[u][v];
                val += fv[tx * 4 + v] * Ub[(size_t)(ty * 4 + u) * NN + ig];  // diag
                if (pre != nullptr) val += pre[o];
                out[o] = val;
            }
        }
    } else {
        // finish values, stage transposed in smem (pitch 68), coalesced write
        float* T = smem;                            // 64 x 68 (4352 <= 8320)
        #pragma unroll
        for (int u = 0; u < 4; u++) {
            int oc = h * 64 + ty * 4 + u;
            #pragma unroll
            for (int v = 0; v < 4; v++) {
                int ig = it + tx * 4 + v;
                float val = acc[u][v];
                val += fv[tx * 4 + v] * Ub[(size_t)(ty * 4 + u) * NN + ig];
                if (pre != nullptr) val += pre[((size_t)b * CDIM + oc) * NN + ig];
                T[(tx * 4 + v) * 68 + ty * 4 + u] = val;
            }
        }
        __syncthreads();
        #pragma unroll
        for (int l = 0; l < 4; l++) {
            int idx = tid + l * 256; int r = idx >> 4, c4 = idx & 15;
            float4 o4 = *(const float4*)&T[r * 68 + c4 * 4];
            *(float4*)&outT[((size_t)(b * NN + it + r)) * CDIM + h * 64 + c4 * 4] = o4;
        }
    }
}

// gts[m,o] = relu(sum_c F[m,c]*W[o,c] + b[o]),  m = b*NN+n
__global__ __launch_bounds__(256) void gts_kernel(
        const float* __restrict__ F, const float* __restrict__ W,
        const float* __restrict__ bias, float* __restrict__ out) {
    int mt = blockIdx.y * 64, ntc = blockIdx.x * 64;
    __shared__ float Fst[64][65];
    __shared__ float Wst[64][65];
    int tid = threadIdx.x, ty = tid >> 4, tx = tid & 15;
    float acc[4][4] = {};
    for (int k0 = 0; k0 < CDIM; k0 += 64) {
        #pragma unroll
        for (int l = 0; l < 4; l++) {
            int idx = tid + l * 256; int r = idx >> 4, c4 = idx & 15;
            float4 f4 = *(const float4*)(F + (size_t)(mt + r) * CDIM + k0 + c4 * 4);
            Fst[c4*4+0][r] = f4.x; Fst[c4*4+1][r] = f4.y; Fst[c4*4+2][r] = f4.z; Fst[c4*4+3][r] = f4.w;
            float4 w4 = *(const float4*)(W + (size_t)(ntc + r) * CDIM + k0 + c4 * 4);
            Wst[c4*4+0][r] = w4.x; Wst[c4*4+1][r] = w4.y; Wst[c4*4+2][r] = w4.z; Wst[c4*4+3][r] = w4.w;
        }
        __syncthreads();
        #pragma unroll 16
        for (int k = 0; k < 64; k++) {
            float a[4], bv[4];
            #pragma unroll
            for (int u = 0; u < 4; u++) a[u]  = Fst[k][ty * 4 + u];
            #pragma unroll
            for (int v = 0; v < 4; v++) bv[v] = Wst[k][tx * 4 + v];
            #pragma unroll
            for (int u = 0; u < 4; u++)
                #pragma unroll
                for (int v = 0; v < 4; v++) acc[u][v] += a[u] * bv[v];
        }
        __syncthreads();
    }
    #pragma unroll
    for (int u = 0; u < 4; u++)
        #pragma unroll
        for (int v = 0; v < 4; v++) {
            int oc = ntc + tx * 4 + v;
            float val = fmaxf(acc[u][v] + bias[oc], 0.0f);
            out[(size_t)(mt + ty * 4 + u) * CDIM + oc] = val;
        }
}

// LayerNorm over channels of y[b,n,c] = o2m[b,c,n]; writes node_feat and out0.
__global__ void final_kernel(const float* __restrict__ o2m,
                             const float* __restrict__ out2pre,
                             const float* __restrict__ lnw, const float* __restrict__ lnb,
                             float* __restrict__ out0, float* __restrict__ outnf) {
    int b = blockIdx.y, n = blockIdx.x;
    int c = threadIdx.x;
    float y = o2m[((size_t)b * CDIM + c) * NN + n];
    __shared__ float s1[256], s2[256];
    s1[c] = y; s2[c] = y * y;
    __syncthreads();
    for (int st = 128; st; st >>= 1) {
        if (c < st) { s1[c] += s1[c + st]; s2[c] += s2[c + st]; }
        __syncthreads();
    }
    float mu  = s1[0] * (1.0f / CDIM);
    float var = s2[0] * (1.0f / CDIM) - mu * mu;
    float rstd = rsqrtf(fmaxf(var, 0.0f) + 1e-6f);
    float nf = (y - mu) * rstd * lnw[c] + lnb[c];
    size_t oidx = ((size_t)b * NN + n) * CDIM + c;
    outnf[oidx] = nf;
    out0[oidx]  = out2pre[((size_t)b * CDIM + c) * NN + n] + nf;
}

// ---------------- launcher ----------------
extern "C" void kernel_launch(void* const* d_in, const int* in_sizes, int n_in,
                              void* d_out, int out_size) {
    (void)in_sizes; (void)n_in; (void)out_size;
    const float* input   = (const float*)d_in[0];
    const int*   mroi    = (const int*)  d_in[1];
    const int*   smask   = (const int*)  d_in[2];
    const float* gt_feat = (const float*)d_in[3];
    const float* w1      = (const float*)d_in[4];
    const float* b1      = (const float*)d_in[5];
    const float* w2      = (const float*)d_in[6];
    const float* b2      = (const float*)d_in[7];
    const float* gt_w    = (const float*)d_in[8];
    const float* gt_b    = (const float*)d_in[9];
    const float* lnw     = (const float*)d_in[10];
    const float* lnb     = (const float*)d_in[11];

    float* out0    = (float*)d_out;                           // out2.T (B,NN,C)
    float* out_gts = out0 + (size_t)BB * NN * CDIM;           // gts
    float* out_nf  = out0 + 2 * (size_t)BB * NN * CDIM;       // node_feat

    float *S, *vec, *cwc, *fmv, *pre, *o1T, *o2m;
    int *cntarr, *allok, *idxc, *cntp, *cntr;
    cudaGetSymbolAddress((void**)&S,      g_S);
    cudaGetSymbolAddress((void**)&cntarr, g_cnt);
    cudaGetSymbolAddress((void**)&allok,  g_allok);
    cudaGetSymbolAddress((void**)&vec,    g_vec);
    cudaGetSymbolAddress((void**)&idxc,   g_idxc);
    cudaGetSymbolAddress((void**)&cwc,    g_cwc);
    cudaGetSymbolAddress((void**)&cntp,   g_cntp);
    cudaGetSymbolAddress((void**)&cntr,   g_cntr);
    cudaGetSymbolAddress((void**)&fmv,    g_fmv);
    cudaGetSymbolAddress((void**)&pre,    g_pre);
    cudaGetSymbolAddress((void**)&o1T,    g_o1T);
    cudaGetSymbolAddress((void**)&o2m,    g_o2m);

    // independent prep
    gts_kernel<<<dim3(CDIM / 64, (BB * NN) / 64), 256>>>(gt_feat, gt_w, gt_b, out_gts);
    compact_kernel<<<BB, NN>>>(smask, idxc, cntp, cntr, fmv, cntarr);   // + zerocnt
    gconv_kernel<<<dim3(NN / 32, GG, BB), 256>>>(input, w1, b1, pre);

    // ---- stage 1 ----
    cos_gemm_sym_kernel<<<dim3(136, BH), 256>>>(input, S, cntarr);
    okfinal_kernel<<<1, NN>>>(cntarr, vec, allok);            // also re-zeroes cnt
    topk_kernel<<<(BH * NN) / 8, 256>>>(S, vec, allok);       // exact fallback
    cwcfill_kernel<<<BB, NN>>>(idxc, cntr, vec, cwc);
    // fused GEMM writes DIRECTLY transposed into o1T (no transpose kernel)
    ogemm_fused_kernel<<<dim3(NN / 64, BH), 256>>>(pre, S, mroi, idxc, cwc, cntp, fmv, pre, nullptr, o1T);

    // ---- stage 2 ----
    gconv_kernel<<<dim3(NN / 32, GG, BB), 256>>>(o1T, w2, b2, pre);      // out2_pre
    cos_gemm_sym_kernel<<<dim3(136, BH), 256>>>(o1T, S, cntarr);
    okfinal_kernel<<<1, NN>>>(cntarr, vec, allok);
    topk_kernel<<<(BH * NN) / 8, 256>>>(S, vec, allok);
    cwcfill_kernel<<<BB, NN>>>(idxc, cntr, vec, cwc);
    ogemm_fused_kernel<<<dim3(NN / 64, BH), 256>>>(pre, S, mroi, idxc, cwc, cntp, fmv, nullptr, o2m, nullptr);
    final_kernel<<<dim3(NN, BB), 256>>>(o2m, pre, lnw, lnb, out0, out_nf);
}